// round 12
// baseline (speedup 1.0000x reference)
#include <cuda_runtime.h>
#include <cuda_bf16.h>
#include <cuda_fp16.h>
#include <math.h>

// Problem constants
#define NTOK 8192   // B*T
#define DDIM 1024   // D
#define LDIM 512    // L
#define VSZ  8192   // V

// Filter margin for the bf16 scorer (see R7 analysis)
#define DELTA 0.02f

// smem row pad (floats) for the tf32 GEMM: bank = (4*row + q) % 32 -> conflict-free
#define PAD 20
// dynamic-smem layout for the double-buffered tf32 GEMM
#define ARR   (128 * PAD)          // floats per array (2560)
#define STAGE (4 * ARR)            // Ah,Al,Bh,Bl per stage (10240 floats)
#define GEMM_SMEM_BYTES (2 * STAGE * 4)   // 81920 bytes

// ---------------- scratch (static __device__ — no runtime allocation) ----------------
__device__ float g_Pin  [NTOK * LDIM];   // x@W_in + b_in (pre-norm)
__device__ float g_A    [NTOK * LDIM];   // l2norm(P_in)          (fp32, exact rescore)
__device__ float g_Pcode[VSZ  * LDIM];   // codebook@W_code + b_code (pre-norm)
__device__ float g_C    [VSZ  * LDIM];   // l2norm(l2norm(P_code)) (fp32, exact rescore)
__device__ __nv_bfloat16 g_Abf[NTOK * LDIM];  // bf16 copy for MMA scorer
__device__ __nv_bfloat16 g_Cbf[VSZ  * LDIM];  // bf16 copy for MMA scorer
__device__ __half g_S[(size_t)NTOK * VSZ];    // approx scores (fp16), 134MB
__device__ float g_b2   [VSZ];           // sum(C*C) per code row (exact)
__device__ unsigned long long g_best[NTOK];   // packed approx min (key<<32 | idx)
__device__ int    g_idx  [NTOK];
__device__ int    g_count[VSZ];
__device__ double g_sum1;                // sum (q - x)^2 over N*D
__device__ double g_sum2;                // sum (Pcode[idx] - Pin)^2 over N*L

// ---------------- helpers ----------------
__device__ __forceinline__ unsigned int fkey(float f) {
    unsigned int u = __float_as_uint(f);
    return (u & 0x80000000u) ? ~u : (u | 0x80000000u);   // order-preserving map
}
__device__ __forceinline__ float keyfloat(unsigned int k) {
    unsigned int u = (k & 0x80000000u) ? (k & 0x7FFFFFFFu) : ~k;
    return __uint_as_float(u);
}

// block sum; all threads receive the result
__device__ __forceinline__ float blockSum(float v, int nthreads) {
    __shared__ float sh[8];
    int lane = threadIdx.x & 31, w = threadIdx.x >> 5, nw = nthreads >> 5;
    #pragma unroll
    for (int o = 16; o; o >>= 1) v += __shfl_down_sync(0xffffffffu, v, o);
    if (lane == 0) sh[w] = v;
    __syncthreads();
    float r = 0.f;
    if (threadIdx.x == 0) {
        for (int i = 0; i < nw; i++) r += sh[i];
        sh[0] = r;
    }
    __syncthreads();
    r = sh[0];
    __syncthreads();
    return r;
}

__device__ __forceinline__ void mma16816(float* c, const unsigned int* a,
                                         unsigned int b0, unsigned int b1) {
    asm volatile(
        "mma.sync.aligned.m16n8k16.row.col.f32.bf16.bf16.f32 "
        "{%0,%1,%2,%3},{%4,%5,%6,%7},{%8,%9},{%0,%1,%2,%3};"
        : "+f"(c[0]), "+f"(c[1]), "+f"(c[2]), "+f"(c[3])
        : "r"(a[0]), "r"(a[1]), "r"(a[2]), "r"(a[3]), "r"(b0), "r"(b1));
}

__device__ __forceinline__ void mma_tf32(float* c, const unsigned int* a,
                                         unsigned int b0, unsigned int b1) {
    asm volatile(
        "mma.sync.aligned.m16n8k8.row.col.f32.tf32.tf32.f32 "
        "{%0,%1,%2,%3},{%4,%5,%6,%7},{%8,%9},{%0,%1,%2,%3};"
        : "+f"(c[0]), "+f"(c[1]), "+f"(c[2]), "+f"(c[3])
        : "r"(a[0]), "r"(a[1]), "r"(a[2]), "r"(a[3]), "r"(b0), "r"(b1));
}

__device__ __forceinline__ float tf32r(float x) {
    float r; asm("cvt.rna.tf32.f32 %0, %1;" : "=f"(r) : "f"(x)); return r;
}

// ---------------- init ----------------
__global__ void k_init() {
    int i = blockIdx.x * blockDim.x + threadIdx.x;
    if (i < VSZ)  g_count[i] = 0;
    if (i < NTOK) g_best[i] = 0xFFFFFFFFFFFFFFFFull;
    if (i == 0) { g_sum1 = 0.0; g_sum2 = 0.0; }
}

// ---------------- fused tf32 3-pass GEMM for BOTH latent projections ----------------
// blockIdx.y < 64: Pin = x @ W_in + b_in ; else: Pcode = cb @ W_code + b_code.
// Both are M=8192, N=512, K=1024. fp32-faithful hi/lo split:
//   D = Ah*Bh + Ah*Bl + Al*Bh (fp32 accumulate).
// Double-buffered dynamic smem (2 x 40KB stages), ONE __syncthreads per chunk:
// compute reads stage kc&1 while split+STS for kc+1 writes stage (kc+1)&1.
__global__ __launch_bounds__(256) void k_gemm2(
    const float* __restrict__ x,  const float* __restrict__ cb,
    const float* __restrict__ Wi, const float* __restrict__ Wc,
    const float* __restrict__ bi, const float* __restrict__ bc,
    float* __restrict__ Pin, float* __restrict__ Pcode)
{
    extern __shared__ __align__(16) float smem[];

    const int tid = threadIdx.x;
    const int lane = tid & 31;
    const int wid = tid >> 5;
    const int warp_m = wid >> 1, warp_n = wid & 1;
    const int g = lane >> 2, q = lane & 3;
    const int by = blockIdx.y;
    const int sel = (by >= 64);
    const int bm0 = (by & 63) * 128, bn0 = blockIdx.x * 128;

    const float* A    = sel ? cb : x;
    const float* B    = sel ? Wc : Wi;
    const float* bias = sel ? bc : bi;
    float*       C    = sel ? Pcode : Pin;
    const int N = LDIM, K = DDIM;

    float acc[2][8][4];
    #pragma unroll
    for (int mt = 0; mt < 2; mt++)
        #pragma unroll
        for (int nt = 0; nt < 8; nt++)
            #pragma unroll
            for (int i = 0; i < 4; i++) acc[mt][nt][i] = 0.f;

    // A loader: each thread owns row = tid>>1, 8 consecutive k at (tid&1)*8
    const int arow = tid >> 1, ahalf = (tid & 1) * 8;
    const float* Ap = A + (size_t)(bm0 + arow) * K + ahalf;
    // B loader: each thread owns column n = tid&127, two k-groups {kg, kg+2}
    const int bn = tid & 127, bkg = tid >> 7;        // bkg in {0,1}
    const float* Bp = B + bn0 + bn;

    // prefetch chunk 0
    float4 av0 = *(const float4*)(Ap);
    float4 av1 = *(const float4*)(Ap + 4);
    float bv[2][4];
    #pragma unroll
    for (int t = 0; t < 2; t++) {
        int kb = (bkg + 2 * t) * 4;
        #pragma unroll
        for (int kk = 0; kk < 4; kk++)
            bv[t][kk] = Bp[(size_t)(kb + kk) * N];
    }

    const int nchunks = K / 16;   // 64

    // split + store current register chunk into given stage
    auto split_store = [&](float* st) {
        float* Ah = st;
        float* Al = st + ARR;
        float* Bh = st + 2 * ARR;
        float* Bl = st + 3 * ARR;
        {
            float va[8] = {av0.x, av0.y, av0.z, av0.w, av1.x, av1.y, av1.z, av1.w};
            float h[8], l[8];
            #pragma unroll
            for (int i = 0; i < 8; i++) {
                h[i] = tf32r(va[i]);
                l[i] = tf32r(va[i] - h[i]);
            }
            int base = arow * PAD + ahalf;
            *(float4*)&Ah[base]     = make_float4(h[0], h[1], h[2], h[3]);
            *(float4*)&Ah[base + 4] = make_float4(h[4], h[5], h[6], h[7]);
            *(float4*)&Al[base]     = make_float4(l[0], l[1], l[2], l[3]);
            *(float4*)&Al[base + 4] = make_float4(l[4], l[5], l[6], l[7]);
        }
        #pragma unroll
        for (int t = 0; t < 2; t++) {
            int kb = (bkg + 2 * t) * 4;
            float h[4], l[4];
            #pragma unroll
            for (int kk = 0; kk < 4; kk++) {
                h[kk] = tf32r(bv[t][kk]);
                l[kk] = tf32r(bv[t][kk] - h[kk]);
            }
            int base = bn * PAD + kb;
            *(float4*)&Bh[base] = make_float4(h[0], h[1], h[2], h[3]);
            *(float4*)&Bl[base] = make_float4(l[0], l[1], l[2], l[3]);
        }
    };

    split_store(smem);        // stage 0
    __syncthreads();

    for (int kc = 0; kc < nchunks; kc++) {
        // issue global prefetch for chunk kc+1 (overlaps with compute below)
        if (kc + 1 < nchunks) {
            int ko = (kc + 1) * 16;
            av0 = *(const float4*)(Ap + ko);
            av1 = *(const float4*)(Ap + ko + 4);
            #pragma unroll
            for (int t = 0; t < 2; t++) {
                int kb = ko + (bkg + 2 * t) * 4;
                #pragma unroll
                for (int kk = 0; kk < 4; kk++)
                    bv[t][kk] = Bp[(size_t)(kb + kk) * N];
            }
        }

        // compute on stage kc&1
        const float* st = smem + (kc & 1) * STAGE;
        const unsigned int* Ah32 = (const unsigned int*)st;
        const unsigned int* Al32 = (const unsigned int*)(st + ARR);
        const unsigned int* Bh32 = (const unsigned int*)(st + 2 * ARR);
        const unsigned int* Bl32 = (const unsigned int*)(st + 3 * ARR);

        #pragma unroll
        for (int ks = 0; ks < 2; ks++) {
            unsigned int ah[2][4], al[2][4];
            #pragma unroll
            for (int mt = 0; mt < 2; mt++) {
                int r = warp_m * 32 + mt * 16 + g;
                int i0 = r * PAD + ks * 8 + q;
                ah[mt][0] = Ah32[i0];
                ah[mt][1] = Ah32[i0 + 8 * PAD];
                ah[mt][2] = Ah32[i0 + 4];
                ah[mt][3] = Ah32[i0 + 8 * PAD + 4];
                al[mt][0] = Al32[i0];
                al[mt][1] = Al32[i0 + 8 * PAD];
                al[mt][2] = Al32[i0 + 4];
                al[mt][3] = Al32[i0 + 8 * PAD + 4];
            }
            #pragma unroll
            for (int nt = 0; nt < 8; nt++) {
                int rc = warp_n * 64 + nt * 8 + g;
                int bi2 = rc * PAD + ks * 8 + q;
                unsigned int bh0 = Bh32[bi2], bh1 = Bh32[bi2 + 4];
                unsigned int bl0 = Bl32[bi2], bl1 = Bl32[bi2 + 4];
                #pragma unroll
                for (int mt = 0; mt < 2; mt++) {
                    mma_tf32(acc[mt][nt], ah[mt], bh0, bh1);
                    mma_tf32(acc[mt][nt], ah[mt], bl0, bl1);
                    mma_tf32(acc[mt][nt], al[mt], bh0, bh1);
                }
            }
        }

        // split+store chunk kc+1 into the OTHER stage (no race with compute above)
        if (kc + 1 < nchunks)
            split_store(smem + ((kc + 1) & 1) * STAGE);
        __syncthreads();
    }

    // epilogue: + bias, float2 stores
    #pragma unroll
    for (int mt = 0; mt < 2; mt++) {
        int row = bm0 + warp_m * 32 + mt * 16 + g;
        #pragma unroll
        for (int nt = 0; nt < 8; nt++) {
            int col = bn0 + warp_n * 64 + nt * 8 + 2 * q;
            float2 bb = *(const float2*)&bias[col];
            float2 c0 = make_float2(acc[mt][nt][0] + bb.x, acc[mt][nt][1] + bb.y);
            float2 c1 = make_float2(acc[mt][nt][2] + bb.x, acc[mt][nt][3] + bb.y);
            *(float2*)&C[(size_t)row * N + col]       = c0;
            *(float2*)&C[(size_t)(row + 8) * N + col] = c1;
        }
    }
}

// ---------------- fused row norms ----------------
// blocks [0, NTOK): tokens -> g_A (single norm) + g_Abf
// blocks [NTOK, NTOK+VSZ): codes -> g_C (double norm) + g_Cbf + g_b2
__global__ void k_norms() {
    int b = blockIdx.x, t = threadIdx.x;
    if (b < NTOK) {
        int rw = b;
        float4 v = ((const float4*)(g_Pin + (size_t)rw * LDIM))[t];
        float s = blockSum(v.x*v.x + v.y*v.y + v.z*v.z + v.w*v.w, 128);
        float r = rsqrtf(s + 1e-12f);
        float4 o = make_float4(v.x*r, v.y*r, v.z*r, v.w*r);
        ((float4*)(g_A + (size_t)rw * LDIM))[t] = o;
        __nv_bfloat162* ob = (__nv_bfloat162*)(g_Abf + (size_t)rw * LDIM);
        ob[t * 2 + 0] = __floats2bfloat162_rn(o.x, o.y);
        ob[t * 2 + 1] = __floats2bfloat162_rn(o.z, o.w);
    } else {
        int rw = b - NTOK;
        float4 v = ((const float4*)(g_Pcode + (size_t)rw * LDIM))[t];
        float s1 = blockSum(v.x*v.x + v.y*v.y + v.z*v.z + v.w*v.w, 128);
        float r1 = rsqrtf(s1 + 1e-12f);
        v = make_float4(v.x*r1, v.y*r1, v.z*r1, v.w*r1);
        float s2 = blockSum(v.x*v.x + v.y*v.y + v.z*v.z + v.w*v.w, 128);
        float r2 = rsqrtf(s2 + 1e-12f);
        v = make_float4(v.x*r2, v.y*r2, v.z*r2, v.w*r2);
        float s3 = blockSum(v.x*v.x + v.y*v.y + v.z*v.z + v.w*v.w, 128);
        ((float4*)(g_C + (size_t)rw * LDIM))[t] = v;
        __nv_bfloat162* ob = (__nv_bfloat162*)(g_Cbf + (size_t)rw * LDIM);
        ob[t * 2 + 0] = __floats2bfloat162_rn(v.x, v.y);
        ob[t * 2 + 1] = __floats2bfloat162_rn(v.z, v.w);
        if (t == 0) g_b2[rw] = s3;
    }
}

// ---------------- bf16 tensor-core scorer ----------------
// Tile 128 tokens x 128 codes, K=512 in 8 chunks of 64. 8 warps: 4(m) x 2(n),
// warp tile 32x64 via mma.m16n8k16 (2 m-tiles x 8 n-tiles).
// Smem: 8x8 uint4-block XOR swizzle -> conflict-free LDS.32 fragment loads.
// Epilogue: s = b2[v] - 2*dot; store fp16 score matrix + per-row approx-min atomicMin.
__global__ __launch_bounds__(256) void k_score() {
    __shared__ __align__(16) __nv_bfloat16 As[128 * 64];
    __shared__ __align__(16) __nv_bfloat16 Cs[128 * 64];
    __shared__ unsigned long long red[128 * 2];

    const int tid = threadIdx.x;
    const int wid = tid >> 5, lane = tid & 31;
    const int warp_m = wid >> 1, warp_n = wid & 1;
    const int g = lane >> 2, q = lane & 3;
    const int bm0 = blockIdx.y * 128;   // token tile
    const int bv0 = blockIdx.x * 128;   // code tile

    float acc[2][8][4];
    #pragma unroll
    for (int mt = 0; mt < 2; mt++)
        #pragma unroll
        for (int nt = 0; nt < 8; nt++)
            #pragma unroll
            for (int i = 0; i < 4; i++) acc[mt][nt][i] = 0.f;

    const uint4* Ag = (const uint4*)(g_Abf + (size_t)bm0 * LDIM);
    const uint4* Cg = (const uint4*)(g_Cbf + (size_t)bv0 * LDIM);
    uint4* As4 = (uint4*)As;
    uint4* Cs4 = (uint4*)Cs;
    const unsigned int* As32 = (const unsigned int*)As;
    const unsigned int* Cs32 = (const unsigned int*)Cs;

    for (int kc = 0; kc < 8; kc++) {
        __syncthreads();   // previous chunk's compute done before overwrite
        #pragma unroll
        for (int i = 0; i < 4; i++) {
            int idx = tid + i * 256;            // 0..1023
            int row = idx >> 3, wq = idx & 7;   // 8 uint4 per 64-elem row
            As4[row * 8 + (wq ^ (row & 7))] = Ag[(size_t)row * 64 + kc * 8 + wq];
            Cs4[row * 8 + (wq ^ (row & 7))] = Cg[(size_t)row * 64 + kc * 8 + wq];
        }
        __syncthreads();
        #pragma unroll
        for (int ks = 0; ks < 4; ks++) {
            unsigned int af[2][4];
            #pragma unroll
            for (int mt = 0; mt < 2; mt++) {
                int r0 = warp_m * 32 + mt * 16 + g;
                int r1 = r0 + 8;
                af[mt][0] = As32[r0*32 + (((ks*2 + 0) ^ (r0 & 7)) << 2) + q];
                af[mt][1] = As32[r1*32 + (((ks*2 + 0) ^ (r1 & 7)) << 2) + q];
                af[mt][2] = As32[r0*32 + (((ks*2 + 1) ^ (r0 & 7)) << 2) + q];
                af[mt][3] = As32[r1*32 + (((ks*2 + 1) ^ (r1 & 7)) << 2) + q];
            }
            #pragma unroll
            for (int nt = 0; nt < 8; nt++) {
                int rc = warp_n * 64 + nt * 8 + g;
                unsigned int b0 = Cs32[rc*32 + (((ks*2 + 0) ^ (rc & 7)) << 2) + q];
                unsigned int b1 = Cs32[rc*32 + (((ks*2 + 1) ^ (rc & 7)) << 2) + q];
                mma16816(acc[0][nt], af[0], b0, b1);
                mma16816(acc[1][nt], af[1], b0, b1);
            }
        }
    }

    // epilogue: scores, fp16 store, per-row approx min
    unsigned long long km[2][2];
    km[0][0] = km[0][1] = km[1][0] = km[1][1] = 0xFFFFFFFFFFFFFFFFull;

    #pragma unroll
    for (int nt = 0; nt < 8; nt++) {
        int colG = bv0 + warp_n * 64 + nt * 8 + q * 2;
        float2 bb = *(const float2*)&g_b2[colG];
        #pragma unroll
        for (int mt = 0; mt < 2; mt++) {
            float s0 = bb.x - 2.f * acc[mt][nt][0];
            float s1 = bb.y - 2.f * acc[mt][nt][1];
            float s2 = bb.x - 2.f * acc[mt][nt][2];
            float s3 = bb.y - 2.f * acc[mt][nt][3];
            int r0 = bm0 + warp_m * 32 + mt * 16 + g;
            *(__half2*)&g_S[(size_t)r0 * VSZ + colG]       = __floats2half2_rn(s0, s1);
            *(__half2*)&g_S[(size_t)(r0 + 8) * VSZ + colG] = __floats2half2_rn(s2, s3);
            unsigned long long p0 =
                ((unsigned long long)fkey(s0) << 32) | (unsigned int)colG;
            unsigned long long p1 =
                ((unsigned long long)fkey(s1) << 32) | (unsigned int)(colG + 1);
            if (p1 < p0) p0 = p1;
            if (p0 < km[mt][0]) km[mt][0] = p0;
            unsigned long long p2 =
                ((unsigned long long)fkey(s2) << 32) | (unsigned int)colG;
            unsigned long long p3 =
                ((unsigned long long)fkey(s3) << 32) | (unsigned int)(colG + 1);
            if (p3 < p2) p2 = p3;
            if (p2 < km[mt][1]) km[mt][1] = p2;
        }
    }
    // reduce across the 4 lanes of each quad (same row)
    #pragma unroll
    for (int mt = 0; mt < 2; mt++)
        #pragma unroll
        for (int h = 0; h < 2; h++) {
            unsigned long long v = km[mt][h];
            #pragma unroll
            for (int off = 1; off < 4; off <<= 1) {
                unsigned long long o = __shfl_xor_sync(0xffffffffu, v, off);
                if (o < v) v = o;
            }
            km[mt][h] = v;
        }
    if (q == 0) {
        #pragma unroll
        for (int mt = 0; mt < 2; mt++)
            #pragma unroll
            for (int h = 0; h < 2; h++) {
                int r = warp_m * 32 + mt * 16 + h * 8 + g;
                red[r * 2 + warp_n] = km[mt][h];
            }
    }
    __syncthreads();
    if (tid < 128) {
        unsigned long long m = red[tid * 2];
        if (red[tid * 2 + 1] < m) m = red[tid * 2 + 1];
        atomicMin(&g_best[bm0 + tid], m);
    }
}

// ---------------- candidate filter + exact fp32 rescore (one block per token) ----------------
__global__ __launch_bounds__(256) void k_select() {
    const int n = blockIdx.x, tid = threadIdx.x;
    __shared__ int cnt;
    __shared__ int cand[256];
    __shared__ unsigned long long bestSh;
    if (tid == 0) { cnt = 0; bestSh = 0xFFFFFFFFFFFFFFFFull; }
    __syncthreads();

    const float thr = keyfloat((unsigned int)(g_best[n] >> 32)) + DELTA;
    const __half2* rowS = (const __half2*)(g_S + (size_t)n * VSZ);
    for (int v2 = tid; v2 < VSZ / 2; v2 += 256) {
        float2 f = __half22float2(rowS[v2]);
        if (f.x <= thr) { int p = atomicAdd(&cnt, 1); if (p < 256) cand[p] = v2 * 2; }
        if (f.y <= thr) { int p = atomicAdd(&cnt, 1); if (p < 256) cand[p] = v2 * 2 + 1; }
    }
    __syncthreads();
    int c = cnt;

    unsigned long long best = 0xFFFFFFFFFFFFFFFFull;
    if (c <= 256) {
        const float* ar = g_A + (size_t)n * LDIM;
        for (int i = 0; i < c; i++) {
            int v = cand[i];
            const float* cr = g_C + (size_t)v * LDIM;
            float part = ar[tid * 2] * cr[tid * 2] + ar[tid * 2 + 1] * cr[tid * 2 + 1];
            float s = blockSum(part, 256);
            float score = g_b2[v] - 2.f * s;
            unsigned long long p =
                ((unsigned long long)fkey(score) << 32) | (unsigned int)v;
            if (p < best) best = p;
        }
    } else {
        // safety fallback (statistically never): full exact scan for this token
        const float* ar = g_A + (size_t)n * LDIM;
        unsigned long long loc = 0xFFFFFFFFFFFFFFFFull;
        for (int v = tid; v < VSZ; v += 256) {
            const float* cr = g_C + (size_t)v * LDIM;
            float s = 0.f;
            for (int d = 0; d < LDIM; d++) s += ar[d] * cr[d];
            float score = g_b2[v] - 2.f * s;
            unsigned long long p =
                ((unsigned long long)fkey(score) << 32) | (unsigned int)v;
            if (p < loc) loc = p;
        }
        atomicMin(&bestSh, loc);
        __syncthreads();
        best = bestSh;
    }

    if (tid == 0) {
        int id = (int)(best & 0xFFFFFFFFull);
        g_idx[n] = id;
        atomicAdd(&g_count[id], 1);
    }
}

// ---------------- quantized_st output + commit MSE ----------------
__global__ void k_quant(const float* __restrict__ x, const float* __restrict__ cb,
                        float* __restrict__ out)
{
    int n = blockIdx.x, t = threadIdx.x;
    int id = g_idx[n];
    float4 xv = ((const float4*)(x  + (size_t)n  * DDIM))[t];
    float4 qv = ((const float4*)(cb + (size_t)id * DDIM))[t];
    float4 d = make_float4(qv.x - xv.x, qv.y - xv.y, qv.z - xv.z, qv.w - xv.w);
    ((float4*)(out + (size_t)n * DDIM))[t] =
        make_float4(xv.x + d.x, xv.y + d.y, xv.z + d.z, xv.w + d.w);
    float loc = d.x*d.x + d.y*d.y + d.z*d.z + d.w*d.w;
    float s = blockSum(loc, 256);
    if (t == 0) atomicAdd(&g_sum1, (double)s);
}

// ---------------- latent-space MSE ----------------
__global__ void k_l2loss() {
    int n = blockIdx.x, t = threadIdx.x;
    int id = g_idx[n];
    float4 a = ((const float4*)(g_Pin   + (size_t)n  * LDIM))[t];
    float4 b = ((const float4*)(g_Pcode + (size_t)id * LDIM))[t];
    float4 d = make_float4(b.x - a.x, b.y - a.y, b.z - a.z, b.w - a.w);
    float loc = d.x*d.x + d.y*d.y + d.z*d.z + d.w*d.w;
    float s = blockSum(loc, 128);
    if (t == 0) atomicAdd(&g_sum2, (double)s);
}

// ---------------- final scalars: loss, perplexity, usage ----------------
__global__ void k_final(float* __restrict__ outScal) {
    __shared__ double shd[256];
    __shared__ int    shi[256];
    int t = threadIdx.x;
    double lp = 0.0;
    int used = 0;
    for (int v = t; v < VSZ; v += 256) {
        int c = g_count[v];
        if (c > 0) used++;
        float p = (float)c * (1.0f / 8192.0f);
        lp += (double)(-(p * logf(p + 1e-10f)));
    }
    shd[t] = lp; shi[t] = used;
    __syncthreads();
    for (int o = 128; o; o >>= 1) {
        if (t < o) { shd[t] += shd[t + o]; shi[t] += shi[t + o]; }
        __syncthreads();
    }
    if (t == 0) {
        float lpf = (float)shd[0];
        float m1 = (float)(g_sum1 / (double)((size_t)NTOK * DDIM));
        float m2 = (float)(g_sum2 / (double)((size_t)NTOK * LDIM));
        float loss = (0.25f * m1 + m1) + (0.25f * m2 + m2) + 0.1f * lpf;
        outScal[0] = loss;
        outScal[1] = expf(lpf);
        outScal[2] = (float)shi[0] / (float)VSZ;
    }
}

// ---------------- launch ----------------
extern "C" void kernel_launch(void* const* d_in, const int* in_sizes, int n_in,
                              void* d_out, int out_size)
{
    (void)in_sizes; (void)n_in;
    const float* x      = (const float*)d_in[0];
    const float* cb     = (const float*)d_in[1];
    const float* W_in   = (const float*)d_in[2];
    const float* b_in   = (const float*)d_in[3];
    const float* W_code = (const float*)d_in[4];
    const float* b_code = (const float*)d_in[5];
    float* out = (float*)d_out;

    void *pPin, *pPcode;
    cudaGetSymbolAddress(&pPin,   g_Pin);
    cudaGetSymbolAddress(&pPcode, g_Pcode);

    // opt-in to >48KB dynamic smem for the double-buffered GEMM (host attr, not an alloc)
    static int smem_set = 0;
    if (!smem_set) {
        cudaFuncSetAttribute(k_gemm2, cudaFuncAttributeMaxDynamicSharedMemorySize,
                             GEMM_SMEM_BYTES);
        smem_set = 1;
    }

    k_init<<<(VSZ + 255) / 256, 256>>>();

    // both latent projections in ONE launch (512 CTAs)
    k_gemm2<<<dim3(LDIM / 128, 128), 256, GEMM_SMEM_BYTES>>>(
        x, cb, W_in, W_code, b_in, b_code, (float*)pPin, (float*)pPcode);

    // both norms in one launch
    k_norms<<<NTOK + VSZ, 128>>>();

    // bf16 tensor-core scoring: fp16 score matrix + approx per-token min
    k_score<<<dim3(VSZ / 128, NTOK / 128), 256>>>();

    // epsilon-filter + exact fp32 rescore -> final indices + histogram
    k_select<<<NTOK, 256>>>();

    k_quant<<<NTOK, 256>>>(x, cb, out);
    k_l2loss<<<NTOK, 128>>>();
    k_final<<<1, 256>>>(out + (out_size - 3));
}

// round 13
// speedup vs baseline: 1.1437x; 1.1437x over previous
#include <cuda_runtime.h>
#include <cuda_bf16.h>
#include <cuda_fp16.h>
#include <math.h>

// Problem constants
#define NTOK 8192   // B*T
#define DDIM 1024   // D
#define LDIM 512    // L
#define VSZ  8192   // V

// Filter margin for the bf16 scorer (see R7 analysis)
#define DELTA 0.02f

// smem row pad (floats) for the tf32 GEMM: bank = (4*row + q) % 32 -> conflict-free
#define PAD 20

// k_score double-buffer geometry: stage = As(16KB) + Cs(16KB)
#define SC_STAGE_BYTES 32768
#define SC_SMEM_BYTES  (2 * SC_STAGE_BYTES)   // 65536 dynamic

// ---------------- scratch (static __device__ — no runtime allocation) ----------------
__device__ float g_Pin  [NTOK * LDIM];   // x@W_in + b_in (pre-norm)
__device__ float g_A    [NTOK * LDIM];   // l2norm(P_in)          (fp32, exact rescore)
__device__ float g_Pcode[VSZ  * LDIM];   // codebook@W_code + b_code (pre-norm)
__device__ float g_C    [VSZ  * LDIM];   // l2norm(l2norm(P_code)) (fp32, exact rescore)
__device__ __nv_bfloat16 g_Abf[NTOK * LDIM];  // bf16 copy for MMA scorer
__device__ __nv_bfloat16 g_Cbf[VSZ  * LDIM];  // bf16 copy for MMA scorer
__device__ __half g_S[(size_t)NTOK * VSZ];    // approx scores (fp16), 134MB
__device__ float g_b2   [VSZ];           // sum(C*C) per code row (exact)
__device__ unsigned long long g_best[NTOK];   // packed approx min (key<<32 | idx)
__device__ int    g_idx  [NTOK];
__device__ int    g_count[VSZ];
__device__ double g_sum1;                // sum (q - x)^2 over N*D
__device__ double g_sum2;                // sum (Pcode[idx] - Pin)^2 over N*L

// ---------------- helpers ----------------
__device__ __forceinline__ unsigned int fkey(float f) {
    unsigned int u = __float_as_uint(f);
    return (u & 0x80000000u) ? ~u : (u | 0x80000000u);   // order-preserving map
}
__device__ __forceinline__ float keyfloat(unsigned int k) {
    unsigned int u = (k & 0x80000000u) ? (k & 0x7FFFFFFFu) : ~k;
    return __uint_as_float(u);
}

// block sum; all threads receive the result
__device__ __forceinline__ float blockSum(float v, int nthreads) {
    __shared__ float sh[8];
    int lane = threadIdx.x & 31, w = threadIdx.x >> 5, nw = nthreads >> 5;
    #pragma unroll
    for (int o = 16; o; o >>= 1) v += __shfl_down_sync(0xffffffffu, v, o);
    if (lane == 0) sh[w] = v;
    __syncthreads();
    float r = 0.f;
    if (threadIdx.x == 0) {
        for (int i = 0; i < nw; i++) r += sh[i];
        sh[0] = r;
    }
    __syncthreads();
    r = sh[0];
    __syncthreads();
    return r;
}

__device__ __forceinline__ void mma16816(float* c, const unsigned int* a,
                                         unsigned int b0, unsigned int b1) {
    asm volatile(
        "mma.sync.aligned.m16n8k16.row.col.f32.bf16.bf16.f32 "
        "{%0,%1,%2,%3},{%4,%5,%6,%7},{%8,%9},{%0,%1,%2,%3};"
        : "+f"(c[0]), "+f"(c[1]), "+f"(c[2]), "+f"(c[3])
        : "r"(a[0]), "r"(a[1]), "r"(a[2]), "r"(a[3]), "r"(b0), "r"(b1));
}

__device__ __forceinline__ void mma_tf32(float* c, const unsigned int* a,
                                         unsigned int b0, unsigned int b1) {
    asm volatile(
        "mma.sync.aligned.m16n8k8.row.col.f32.tf32.tf32.f32 "
        "{%0,%1,%2,%3},{%4,%5,%6,%7},{%8,%9},{%0,%1,%2,%3};"
        : "+f"(c[0]), "+f"(c[1]), "+f"(c[2]), "+f"(c[3])
        : "r"(a[0]), "r"(a[1]), "r"(a[2]), "r"(a[3]), "r"(b0), "r"(b1));
}

__device__ __forceinline__ float tf32r(float x) {
    float r; asm("cvt.rna.tf32.f32 %0, %1;" : "=f"(r) : "f"(x)); return r;
}

__device__ __forceinline__ void cp16(unsigned int dst_smem, const void* src) {
    asm volatile("cp.async.cg.shared.global [%0], [%1], 16;\n"
                 :: "r"(dst_smem), "l"(src));
}
#define CP_COMMIT() asm volatile("cp.async.commit_group;\n" ::)
#define CP_WAIT(N)  asm volatile("cp.async.wait_group %0;\n" :: "n"(N))

// ---------------- init ----------------
__global__ void k_init() {
    int i = blockIdx.x * blockDim.x + threadIdx.x;
    if (i < VSZ)  g_count[i] = 0;
    if (i < NTOK) g_best[i] = 0xFFFFFFFFFFFFFFFFull;
    if (i == 0) { g_sum1 = 0.0; g_sum2 = 0.0; }
}

// ---------------- tf32 3-pass GEMM: C[M,N] = A[M,K] @ B[K,N] + bias[N] ----------------
// (R8 version, unchanged — known 179us per launch)
__global__ __launch_bounds__(256) void k_gemm_tf32(
    const float* __restrict__ A, const float* __restrict__ B,
    const float* __restrict__ bias, float* __restrict__ C,
    int M, int N, int K)
{
    __shared__ __align__(16) float Ah[128 * PAD], Al[128 * PAD];
    __shared__ __align__(16) float Bh[128 * PAD], Bl[128 * PAD];

    const int tid = threadIdx.x;
    const int lane = tid & 31;
    const int wid = tid >> 5;
    const int warp_m = wid >> 1, warp_n = wid & 1;
    const int g = lane >> 2, q = lane & 3;
    const int bm0 = blockIdx.y * 128, bn0 = blockIdx.x * 128;

    float acc[2][8][4];
    #pragma unroll
    for (int mt = 0; mt < 2; mt++)
        #pragma unroll
        for (int nt = 0; nt < 8; nt++)
            #pragma unroll
            for (int i = 0; i < 4; i++) acc[mt][nt][i] = 0.f;

    const int arow = tid >> 1, ahalf = (tid & 1) * 8;
    const float* Ap = A + (size_t)(bm0 + arow) * K + ahalf;
    const int bn = tid & 127, bkg = tid >> 7;
    const float* Bp = B + bn0 + bn;

    float4 av0 = *(const float4*)(Ap);
    float4 av1 = *(const float4*)(Ap + 4);
    float bv[2][4];
    #pragma unroll
    for (int t = 0; t < 2; t++) {
        int kb = (bkg + 2 * t) * 4;
        #pragma unroll
        for (int kk = 0; kk < 4; kk++)
            bv[t][kk] = Bp[(size_t)(kb + kk) * N];
    }

    const unsigned int* Ah32 = (const unsigned int*)Ah;
    const unsigned int* Al32 = (const unsigned int*)Al;
    const unsigned int* Bh32 = (const unsigned int*)Bh;
    const unsigned int* Bl32 = (const unsigned int*)Bl;

    const int nchunks = K / 16;
    for (int kc = 0; kc < nchunks; kc++) {
        {
            float va[8] = {av0.x, av0.y, av0.z, av0.w, av1.x, av1.y, av1.z, av1.w};
            float h[8], l[8];
            #pragma unroll
            for (int i = 0; i < 8; i++) {
                h[i] = tf32r(va[i]);
                l[i] = tf32r(va[i] - h[i]);
            }
            int base = arow * PAD + ahalf;
            *(float4*)&Ah[base]     = make_float4(h[0], h[1], h[2], h[3]);
            *(float4*)&Ah[base + 4] = make_float4(h[4], h[5], h[6], h[7]);
            *(float4*)&Al[base]     = make_float4(l[0], l[1], l[2], l[3]);
            *(float4*)&Al[base + 4] = make_float4(l[4], l[5], l[6], l[7]);
        }
        #pragma unroll
        for (int t = 0; t < 2; t++) {
            int kb = (bkg + 2 * t) * 4;
            float h[4], l[4];
            #pragma unroll
            for (int kk = 0; kk < 4; kk++) {
                h[kk] = tf32r(bv[t][kk]);
                l[kk] = tf32r(bv[t][kk] - h[kk]);
            }
            int base = bn * PAD + kb;
            *(float4*)&Bh[base] = make_float4(h[0], h[1], h[2], h[3]);
            *(float4*)&Bl[base] = make_float4(l[0], l[1], l[2], l[3]);
        }
        __syncthreads();

        if (kc + 1 < nchunks) {
            int ko = (kc + 1) * 16;
            av0 = *(const float4*)(Ap + ko);
            av1 = *(const float4*)(Ap + ko + 4);
            #pragma unroll
            for (int t = 0; t < 2; t++) {
                int kb = ko + (bkg + 2 * t) * 4;
                #pragma unroll
                for (int kk = 0; kk < 4; kk++)
                    bv[t][kk] = Bp[(size_t)(kb + kk) * N];
            }
        }

        #pragma unroll
        for (int ks = 0; ks < 2; ks++) {
            unsigned int ah[2][4], al[2][4];
            #pragma unroll
            for (int mt = 0; mt < 2; mt++) {
                int r = warp_m * 32 + mt * 16 + g;
                int i0 = r * PAD + ks * 8 + q;
                ah[mt][0] = Ah32[i0];
                ah[mt][1] = Ah32[i0 + 8 * PAD];
                ah[mt][2] = Ah32[i0 + 4];
                ah[mt][3] = Ah32[i0 + 8 * PAD + 4];
                al[mt][0] = Al32[i0];
                al[mt][1] = Al32[i0 + 8 * PAD];
                al[mt][2] = Al32[i0 + 4];
                al[mt][3] = Al32[i0 + 8 * PAD + 4];
            }
            #pragma unroll
            for (int nt = 0; nt < 8; nt++) {
                int rc = warp_n * 64 + nt * 8 + g;
                int bi = rc * PAD + ks * 8 + q;
                unsigned int bh0 = Bh32[bi], bh1 = Bh32[bi + 4];
                unsigned int bl0 = Bl32[bi], bl1 = Bl32[bi + 4];
                #pragma unroll
                for (int mt = 0; mt < 2; mt++) {
                    mma_tf32(acc[mt][nt], ah[mt], bh0, bh1);
                    mma_tf32(acc[mt][nt], ah[mt], bl0, bl1);
                    mma_tf32(acc[mt][nt], al[mt], bh0, bh1);
                }
            }
        }
        __syncthreads();
    }

    #pragma unroll
    for (int mt = 0; mt < 2; mt++) {
        int row = bm0 + warp_m * 32 + mt * 16 + g;
        #pragma unroll
        for (int nt = 0; nt < 8; nt++) {
            int col = bn0 + warp_n * 64 + nt * 8 + 2 * q;
            float2 bb = *(const float2*)&bias[col];
            float2 c0 = make_float2(acc[mt][nt][0] + bb.x, acc[mt][nt][1] + bb.y);
            float2 c1 = make_float2(acc[mt][nt][2] + bb.x, acc[mt][nt][3] + bb.y);
            *(float2*)&C[(size_t)row * N + col]       = c0;
            *(float2*)&C[(size_t)(row + 8) * N + col] = c1;
        }
    }
}

// ---------------- row L2 norm for tokens: g_Pin -> g_A (fp32) + g_Abf (bf16) ----------------
__global__ void k_rownorm() {
    int rw = blockIdx.x, t = threadIdx.x;
    float4 v = ((const float4*)(g_Pin + (size_t)rw * LDIM))[t];
    float s = blockSum(v.x*v.x + v.y*v.y + v.z*v.z + v.w*v.w, 128);
    float r = rsqrtf(s + 1e-12f);
    float4 o = make_float4(v.x*r, v.y*r, v.z*r, v.w*r);
    ((float4*)(g_A + (size_t)rw * LDIM))[t] = o;
    __nv_bfloat162* ob = (__nv_bfloat162*)(g_Abf + (size_t)rw * LDIM);
    ob[t * 2 + 0] = __floats2bfloat162_rn(o.x, o.y);
    ob[t * 2 + 1] = __floats2bfloat162_rn(o.z, o.w);
}

// codes: double normalization (matches reference), exact ||b||^2, fp32 + bf16 copies
__global__ void k_codenorm() {
    int rw = blockIdx.x, t = threadIdx.x;
    float4 v = ((const float4*)(g_Pcode + (size_t)rw * LDIM))[t];
    float s1 = blockSum(v.x*v.x + v.y*v.y + v.z*v.z + v.w*v.w, 128);
    float r1 = rsqrtf(s1 + 1e-12f);
    v = make_float4(v.x*r1, v.y*r1, v.z*r1, v.w*r1);
    float s2 = blockSum(v.x*v.x + v.y*v.y + v.z*v.z + v.w*v.w, 128);
    float r2 = rsqrtf(s2 + 1e-12f);
    v = make_float4(v.x*r2, v.y*r2, v.z*r2, v.w*r2);
    float s3 = blockSum(v.x*v.x + v.y*v.y + v.z*v.z + v.w*v.w, 128);
    ((float4*)(g_C + (size_t)rw * LDIM))[t] = v;
    __nv_bfloat162* ob = (__nv_bfloat162*)(g_Cbf + (size_t)rw * LDIM);
    ob[t * 2 + 0] = __floats2bfloat162_rn(v.x, v.y);
    ob[t * 2 + 1] = __floats2bfloat162_rn(v.z, v.w);
    if (t == 0) g_b2[rw] = s3;
}

// ---------------- bf16 tensor-core scorer, cp.async depth-2 pipeline ----------------
// Tile 128 tokens x 128 codes, K=512 in 8 chunks of 64. 8 warps: 4(m) x 2(n).
// Double-buffered dynamic smem stages filled by cp.async (LDGSTS): chunk kc+1
// streams in while chunk kc computes — no exposed LDG latency, no LDG/STS pairs.
// Same 8x8 uint4-block XOR swizzle -> conflict-free LDS.32 fragment loads.
__global__ __launch_bounds__(256) void k_score() {
    extern __shared__ __align__(16) char dsm[];
    __shared__ unsigned long long red[128 * 2];

    const int tid = threadIdx.x;
    const int wid = tid >> 5, lane = tid & 31;
    const int warp_m = wid >> 1, warp_n = wid & 1;
    const int g = lane >> 2, q = lane & 3;
    const int bm0 = blockIdx.y * 128;   // token tile
    const int bv0 = blockIdx.x * 128;   // code tile

    float acc[2][8][4];
    #pragma unroll
    for (int mt = 0; mt < 2; mt++)
        #pragma unroll
        for (int nt = 0; nt < 8; nt++)
            #pragma unroll
            for (int i = 0; i < 4; i++) acc[mt][nt][i] = 0.f;

    const uint4* Ag = (const uint4*)(g_Abf + (size_t)bm0 * LDIM);
    const uint4* Cg = (const uint4*)(g_Cbf + (size_t)bv0 * LDIM);
    const unsigned int sbase = (unsigned int)__cvta_generic_to_shared(dsm);

    // per-thread loader mapping (4 x 16B per array per chunk)
    int lrow[4], lwq[4];
    unsigned int ldst[4];
    #pragma unroll
    for (int i = 0; i < 4; i++) {
        int idx = tid + i * 256;            // 0..1023
        lrow[i] = idx >> 3;                 // 0..127
        lwq[i]  = idx & 7;                  // 0..7
        ldst[i] = (unsigned int)((lrow[i] * 8 + (lwq[i] ^ (lrow[i] & 7))) * 16);
    }

    // issue chunk kc into stage kc&1
    auto issue = [&](int kc) {
        unsigned int ab = sbase + (kc & 1) * SC_STAGE_BYTES;
        unsigned int cb2 = ab + 16384;
        #pragma unroll
        for (int i = 0; i < 4; i++) {
            const uint4* sa = Ag + (size_t)lrow[i] * 64 + kc * 8 + lwq[i];
            const uint4* sc = Cg + (size_t)lrow[i] * 64 + kc * 8 + lwq[i];
            cp16(ab  + ldst[i], sa);
            cp16(cb2 + ldst[i], sc);
        }
        CP_COMMIT();
    };

    issue(0);
    #pragma unroll
    for (int kc = 0; kc < 8; kc++) {
        if (kc + 1 < 8) { issue(kc + 1); CP_WAIT(1); }
        else            { CP_WAIT(0); }
        __syncthreads();   // chunk kc data visible to all warps

        const char* st = dsm + (kc & 1) * SC_STAGE_BYTES;
        const unsigned int* As32 = (const unsigned int*)st;
        const unsigned int* Cs32 = (const unsigned int*)(st + 16384);

        #pragma unroll
        for (int ks = 0; ks < 4; ks++) {
            unsigned int af[2][4];
            #pragma unroll
            for (int mt = 0; mt < 2; mt++) {
                int r0 = warp_m * 32 + mt * 16 + g;
                int r1 = r0 + 8;
                af[mt][0] = As32[r0*32 + (((ks*2 + 0) ^ (r0 & 7)) << 2) + q];
                af[mt][1] = As32[r1*32 + (((ks*2 + 0) ^ (r1 & 7)) << 2) + q];
                af[mt][2] = As32[r0*32 + (((ks*2 + 1) ^ (r0 & 7)) << 2) + q];
                af[mt][3] = As32[r1*32 + (((ks*2 + 1) ^ (r1 & 7)) << 2) + q];
            }
            #pragma unroll
            for (int nt = 0; nt < 8; nt++) {
                int rc = warp_n * 64 + nt * 8 + g;
                unsigned int b0 = Cs32[rc*32 + (((ks*2 + 0) ^ (rc & 7)) << 2) + q];
                unsigned int b1 = Cs32[rc*32 + (((ks*2 + 1) ^ (rc & 7)) << 2) + q];
                mma16816(acc[0][nt], af[0], b0, b1);
                mma16816(acc[1][nt], af[1], b0, b1);
            }
        }
        __syncthreads();   // all warps done reading stage kc&1 before it's refilled
    }

    // epilogue: scores, fp16 store, per-row approx min
    unsigned long long km[2][2];
    km[0][0] = km[0][1] = km[1][0] = km[1][1] = 0xFFFFFFFFFFFFFFFFull;

    #pragma unroll
    for (int nt = 0; nt < 8; nt++) {
        int colG = bv0 + warp_n * 64 + nt * 8 + q * 2;
        float2 bb = *(const float2*)&g_b2[colG];
        #pragma unroll
        for (int mt = 0; mt < 2; mt++) {
            float s0 = bb.x - 2.f * acc[mt][nt][0];
            float s1 = bb.y - 2.f * acc[mt][nt][1];
            float s2 = bb.x - 2.f * acc[mt][nt][2];
            float s3 = bb.y - 2.f * acc[mt][nt][3];
            int r0 = bm0 + warp_m * 32 + mt * 16 + g;
            *(__half2*)&g_S[(size_t)r0 * VSZ + colG]       = __floats2half2_rn(s0, s1);
            *(__half2*)&g_S[(size_t)(r0 + 8) * VSZ + colG] = __floats2half2_rn(s2, s3);
            unsigned long long p0 =
                ((unsigned long long)fkey(s0) << 32) | (unsigned int)colG;
            unsigned long long p1 =
                ((unsigned long long)fkey(s1) << 32) | (unsigned int)(colG + 1);
            if (p1 < p0) p0 = p1;
            if (p0 < km[mt][0]) km[mt][0] = p0;
            unsigned long long p2 =
                ((unsigned long long)fkey(s2) << 32) | (unsigned int)colG;
            unsigned long long p3 =
                ((unsigned long long)fkey(s3) << 32) | (unsigned int)(colG + 1);
            if (p3 < p2) p2 = p3;
            if (p2 < km[mt][1]) km[mt][1] = p2;
        }
    }
    #pragma unroll
    for (int mt = 0; mt < 2; mt++)
        #pragma unroll
        for (int h = 0; h < 2; h++) {
            unsigned long long v = km[mt][h];
            #pragma unroll
            for (int off = 1; off < 4; off <<= 1) {
                unsigned long long o = __shfl_xor_sync(0xffffffffu, v, off);
                if (o < v) v = o;
            }
            km[mt][h] = v;
        }
    if (q == 0) {
        #pragma unroll
        for (int mt = 0; mt < 2; mt++)
            #pragma unroll
            for (int h = 0; h < 2; h++) {
                int r = warp_m * 32 + mt * 16 + h * 8 + g;
                red[r * 2 + warp_n] = km[mt][h];
            }
    }
    __syncthreads();
    if (tid < 128) {
        unsigned long long m = red[tid * 2];
        if (red[tid * 2 + 1] < m) m = red[tid * 2 + 1];
        atomicMin(&g_best[bm0 + tid], m);
    }
}

// ---------------- candidate filter + exact fp32 rescore (one block per token) ----------------
__global__ __launch_bounds__(256) void k_select() {
    const int n = blockIdx.x, tid = threadIdx.x;
    __shared__ int cnt;
    __shared__ int cand[256];
    __shared__ unsigned long long bestSh;
    if (tid == 0) { cnt = 0; bestSh = 0xFFFFFFFFFFFFFFFFull; }
    __syncthreads();

    const float thr = keyfloat((unsigned int)(g_best[n] >> 32)) + DELTA;
    const __half2* rowS = (const __half2*)(g_S + (size_t)n * VSZ);
    for (int v2 = tid; v2 < VSZ / 2; v2 += 256) {
        float2 f = __half22float2(rowS[v2]);
        if (f.x <= thr) { int p = atomicAdd(&cnt, 1); if (p < 256) cand[p] = v2 * 2; }
        if (f.y <= thr) { int p = atomicAdd(&cnt, 1); if (p < 256) cand[p] = v2 * 2 + 1; }
    }
    __syncthreads();
    int c = cnt;

    unsigned long long best = 0xFFFFFFFFFFFFFFFFull;
    if (c <= 256) {
        const float* ar = g_A + (size_t)n * LDIM;
        for (int i = 0; i < c; i++) {
            int v = cand[i];
            const float* cr = g_C + (size_t)v * LDIM;
            float part = ar[tid * 2] * cr[tid * 2] + ar[tid * 2 + 1] * cr[tid * 2 + 1];
            float s = blockSum(part, 256);
            float score = g_b2[v] - 2.f * s;
            unsigned long long p =
                ((unsigned long long)fkey(score) << 32) | (unsigned int)v;
            if (p < best) best = p;
        }
    } else {
        // safety fallback (statistically never): full exact scan for this token
        const float* ar = g_A + (size_t)n * LDIM;
        unsigned long long loc = 0xFFFFFFFFFFFFFFFFull;
        for (int v = tid; v < VSZ; v += 256) {
            const float* cr = g_C + (size_t)v * LDIM;
            float s = 0.f;
            for (int d = 0; d < LDIM; d++) s += ar[d] * cr[d];
            float score = g_b2[v] - 2.f * s;
            unsigned long long p =
                ((unsigned long long)fkey(score) << 32) | (unsigned int)v;
            if (p < loc) loc = p;
        }
        atomicMin(&bestSh, loc);
        __syncthreads();
        best = bestSh;
    }

    if (tid == 0) {
        int id = (int)(best & 0xFFFFFFFFull);
        g_idx[n] = id;
        atomicAdd(&g_count[id], 1);
    }
}

// ---------------- quantized_st output + commit MSE ----------------
__global__ void k_quant(const float* __restrict__ x, const float* __restrict__ cb,
                        float* __restrict__ out)
{
    int n = blockIdx.x, t = threadIdx.x;
    int id = g_idx[n];
    float4 xv = ((const float4*)(x  + (size_t)n  * DDIM))[t];
    float4 qv = ((const float4*)(cb + (size_t)id * DDIM))[t];
    float4 d = make_float4(qv.x - xv.x, qv.y - xv.y, qv.z - xv.z, qv.w - xv.w);
    ((float4*)(out + (size_t)n * DDIM))[t] =
        make_float4(xv.x + d.x, xv.y + d.y, xv.z + d.z, xv.w + d.w);
    float loc = d.x*d.x + d.y*d.y + d.z*d.z + d.w*d.w;
    float s = blockSum(loc, 256);
    if (t == 0) atomicAdd(&g_sum1, (double)s);
}

// ---------------- latent-space MSE ----------------
__global__ void k_l2loss() {
    int n = blockIdx.x, t = threadIdx.x;
    int id = g_idx[n];
    float4 a = ((const float4*)(g_Pin   + (size_t)n  * LDIM))[t];
    float4 b = ((const float4*)(g_Pcode + (size_t)id * LDIM))[t];
    float4 d = make_float4(b.x - a.x, b.y - a.y, b.z - a.z, b.w - a.w);
    float loc = d.x*d.x + d.y*d.y + d.z*d.z + d.w*d.w;
    float s = blockSum(loc, 128);
    if (t == 0) atomicAdd(&g_sum2, (double)s);
}

// ---------------- final scalars: loss, perplexity, usage ----------------
__global__ void k_final(float* __restrict__ outScal) {
    __shared__ double shd[256];
    __shared__ int    shi[256];
    int t = threadIdx.x;
    double lp = 0.0;
    int used = 0;
    for (int v = t; v < VSZ; v += 256) {
        int c = g_count[v];
        if (c > 0) used++;
        float p = (float)c * (1.0f / 8192.0f);
        lp += (double)(-(p * logf(p + 1e-10f)));
    }
    shd[t] = lp; shi[t] = used;
    __syncthreads();
    for (int o = 128; o; o >>= 1) {
        if (t < o) { shd[t] += shd[t + o]; shi[t] += shi[t + o]; }
        __syncthreads();
    }
    if (t == 0) {
        float lpf = (float)shd[0];
        float m1 = (float)(g_sum1 / (double)((size_t)NTOK * DDIM));
        float m2 = (float)(g_sum2 / (double)((size_t)NTOK * LDIM));
        float loss = (0.25f * m1 + m1) + (0.25f * m2 + m2) + 0.1f * lpf;
        outScal[0] = loss;
        outScal[1] = expf(lpf);
        outScal[2] = (float)shi[0] / (float)VSZ;
    }
}

// ---------------- launch ----------------
extern "C" void kernel_launch(void* const* d_in, const int* in_sizes, int n_in,
                              void* d_out, int out_size)
{
    (void)in_sizes; (void)n_in;
    const float* x      = (const float*)d_in[0];
    const float* cb     = (const float*)d_in[1];
    const float* W_in   = (const float*)d_in[2];
    const float* b_in   = (const float*)d_in[3];
    const float* W_code = (const float*)d_in[4];
    const float* b_code = (const float*)d_in[5];
    float* out = (float*)d_out;

    void *pPin, *pPcode;
    cudaGetSymbolAddress(&pPin,   g_Pin);
    cudaGetSymbolAddress(&pPcode, g_Pcode);

    // opt-in to 64KB dynamic smem for k_score (host attr — deterministic, no alloc)
    cudaFuncSetAttribute(k_score, cudaFuncAttributeMaxDynamicSharedMemorySize,
                         SC_SMEM_BYTES);

    k_init<<<(VSZ + 255) / 256, 256>>>();

    // latent_input = l2norm(x @ W_in + b_in); fp32-faithful tf32 3-pass GEMM
    k_gemm_tf32<<<dim3(LDIM / 128, NTOK / 128), 256>>>(
        x, W_in, b_in, (float*)pPin, NTOK, LDIM, DDIM);
    k_rownorm<<<NTOK, 128>>>();

    // latent_code (double-normalized) + exact ||b||^2
    k_gemm_tf32<<<dim3(LDIM / 128, VSZ / 128), 256>>>(
        cb, W_code, b_code, (float*)pPcode, VSZ, LDIM, DDIM);
    k_codenorm<<<VSZ, 128>>>();

    // bf16 tensor-core scoring (cp.async pipelined): fp16 scores + approx min
    k_score<<<dim3(VSZ / 128, NTOK / 128), 256, SC_SMEM_BYTES>>>();

    // epsilon-filter + exact fp32 rescore -> final indices + histogram
    k_select<<<NTOK, 256>>>();

    k_quant<<<NTOK, 256>>>(x, cb, out);
    k_l2loss<<<NTOK, 128>>>();
    k_final<<<1, 256>>>(out + (out_size - 3));
}

// round 14
// speedup vs baseline: 1.2705x; 1.1108x over previous
#include <cuda_runtime.h>
#include <cuda_bf16.h>
#include <cuda_fp16.h>
#include <math.h>

// Problem constants
#define NTOK 8192   // B*T
#define DDIM 1024   // D
#define LDIM 512    // L
#define VSZ  8192   // V
#define NTILE (VSZ / 128)   // 64 code tiles per token row

// Filter margin for the bf16 scorer (see R7 analysis)
#define DELTA 0.02f

// smem row pad (floats) for the tf32 GEMM: bank = (4*row + q) % 32 -> conflict-free
#define PAD 20

// k_score double-buffer geometry: stage = As(16KB) + Cs(16KB)
#define SC_STAGE_BYTES 32768
#define SC_SMEM_BYTES  (2 * SC_STAGE_BYTES)   // 65536 dynamic

// ---------------- scratch (static __device__ — no runtime allocation) ----------------
__device__ float g_Pin  [NTOK * LDIM];   // x@W_in + b_in (pre-norm)
__device__ float g_A    [NTOK * LDIM];   // l2norm(P_in)          (fp32, exact rescore)
__device__ float g_Pcode[VSZ  * LDIM];   // codebook@W_code + b_code (pre-norm)
__device__ float g_C    [VSZ  * LDIM];   // l2norm(l2norm(P_code)) (fp32, exact rescore)
__device__ __nv_bfloat16 g_Abf[NTOK * LDIM];  // bf16 copy for MMA scorer
__device__ __nv_bfloat16 g_Cbf[VSZ  * LDIM];  // bf16 copy for MMA scorer
__device__ __half g_S[(size_t)NTOK * VSZ];    // approx scores (fp16), 134MB
__device__ float g_tmin[NTOK * NTILE];   // per (token, code-tile) approx min (2MB)
__device__ float g_b2   [VSZ];           // sum(C*C) per code row (exact)
__device__ unsigned long long g_best[NTOK];   // packed approx min (key<<32 | idx)
__device__ int    g_idx  [NTOK];
__device__ int    g_count[VSZ];
__device__ double g_sum1;                // sum (q - x)^2 over N*D
__device__ double g_sum2;                // sum (Pcode[idx] - Pin)^2 over N*L

// ---------------- helpers ----------------
__device__ __forceinline__ unsigned int fkey(float f) {
    unsigned int u = __float_as_uint(f);
    return (u & 0x80000000u) ? ~u : (u | 0x80000000u);   // order-preserving map
}
__device__ __forceinline__ float keyfloat(unsigned int k) {
    unsigned int u = (k & 0x80000000u) ? (k & 0x7FFFFFFFu) : ~k;
    return __uint_as_float(u);
}

// block sum; all threads receive the result
__device__ __forceinline__ float blockSum(float v, int nthreads) {
    __shared__ float sh[8];
    int lane = threadIdx.x & 31, w = threadIdx.x >> 5, nw = nthreads >> 5;
    #pragma unroll
    for (int o = 16; o; o >>= 1) v += __shfl_down_sync(0xffffffffu, v, o);
    if (lane == 0) sh[w] = v;
    __syncthreads();
    float r = 0.f;
    if (threadIdx.x == 0) {
        for (int i = 0; i < nw; i++) r += sh[i];
        sh[0] = r;
    }
    __syncthreads();
    r = sh[0];
    __syncthreads();
    return r;
}

__device__ __forceinline__ void mma16816(float* c, const unsigned int* a,
                                         unsigned int b0, unsigned int b1) {
    asm volatile(
        "mma.sync.aligned.m16n8k16.row.col.f32.bf16.bf16.f32 "
        "{%0,%1,%2,%3},{%4,%5,%6,%7},{%8,%9},{%0,%1,%2,%3};"
        : "+f"(c[0]), "+f"(c[1]), "+f"(c[2]), "+f"(c[3])
        : "r"(a[0]), "r"(a[1]), "r"(a[2]), "r"(a[3]), "r"(b0), "r"(b1));
}

__device__ __forceinline__ void mma_tf32(float* c, const unsigned int* a,
                                         unsigned int b0, unsigned int b1) {
    asm volatile(
        "mma.sync.aligned.m16n8k8.row.col.f32.tf32.tf32.f32 "
        "{%0,%1,%2,%3},{%4,%5,%6,%7},{%8,%9},{%0,%1,%2,%3};"
        : "+f"(c[0]), "+f"(c[1]), "+f"(c[2]), "+f"(c[3])
        : "r"(a[0]), "r"(a[1]), "r"(a[2]), "r"(a[3]), "r"(b0), "r"(b1));
}

__device__ __forceinline__ float tf32r(float x) {
    float r; asm("cvt.rna.tf32.f32 %0, %1;" : "=f"(r) : "f"(x)); return r;
}

__device__ __forceinline__ void cp16(unsigned int dst_smem, const void* src) {
    asm volatile("cp.async.cg.shared.global [%0], [%1], 16;\n"
                 :: "r"(dst_smem), "l"(src));
}
#define CP_COMMIT() asm volatile("cp.async.commit_group;\n" ::)
#define CP_WAIT(N)  asm volatile("cp.async.wait_group %0;\n" :: "n"(N))

// ---------------- init ----------------
__global__ void k_init() {
    int i = blockIdx.x * blockDim.x + threadIdx.x;
    if (i < VSZ)  g_count[i] = 0;
    if (i < NTOK) g_best[i] = 0xFFFFFFFFFFFFFFFFull;
    if (i == 0) { g_sum1 = 0.0; g_sum2 = 0.0; }
}

// ---------------- tf32 3-pass GEMM: C[M,N] = A[M,K] @ B[K,N] + bias[N] ----------------
// fp32-faithful hi/lo split: D = Ah*Bh + Ah*Bl + Al*Bh (fp32 accumulate).
// R14: __launch_bounds__(256,2) caps regs at 128 -> 2 CTAs/SM, single wave of 256.
__global__ __launch_bounds__(256, 2) void k_gemm_tf32(
    const float* __restrict__ A, const float* __restrict__ B,
    const float* __restrict__ bias, float* __restrict__ C,
    int M, int N, int K)
{
    __shared__ __align__(16) float Ah[128 * PAD], Al[128 * PAD];
    __shared__ __align__(16) float Bh[128 * PAD], Bl[128 * PAD];

    const int tid = threadIdx.x;
    const int lane = tid & 31;
    const int wid = tid >> 5;
    const int warp_m = wid >> 1, warp_n = wid & 1;
    const int g = lane >> 2, q = lane & 3;
    const int bm0 = blockIdx.y * 128, bn0 = blockIdx.x * 128;

    float acc[2][8][4];
    #pragma unroll
    for (int mt = 0; mt < 2; mt++)
        #pragma unroll
        for (int nt = 0; nt < 8; nt++)
            #pragma unroll
            for (int i = 0; i < 4; i++) acc[mt][nt][i] = 0.f;

    const int arow = tid >> 1, ahalf = (tid & 1) * 8;
    const float* Ap = A + (size_t)(bm0 + arow) * K + ahalf;
    const int bn = tid & 127, bkg = tid >> 7;
    const float* Bp = B + bn0 + bn;

    float4 av0 = *(const float4*)(Ap);
    float4 av1 = *(const float4*)(Ap + 4);
    float bv[2][4];
    #pragma unroll
    for (int t = 0; t < 2; t++) {
        int kb = (bkg + 2 * t) * 4;
        #pragma unroll
        for (int kk = 0; kk < 4; kk++)
            bv[t][kk] = Bp[(size_t)(kb + kk) * N];
    }

    const unsigned int* Ah32 = (const unsigned int*)Ah;
    const unsigned int* Al32 = (const unsigned int*)Al;
    const unsigned int* Bh32 = (const unsigned int*)Bh;
    const unsigned int* Bl32 = (const unsigned int*)Bl;

    const int nchunks = K / 16;
    for (int kc = 0; kc < nchunks; kc++) {
        {
            float va[8] = {av0.x, av0.y, av0.z, av0.w, av1.x, av1.y, av1.z, av1.w};
            float h[8], l[8];
            #pragma unroll
            for (int i = 0; i < 8; i++) {
                h[i] = tf32r(va[i]);
                l[i] = tf32r(va[i] - h[i]);
            }
            int base = arow * PAD + ahalf;
            *(float4*)&Ah[base]     = make_float4(h[0], h[1], h[2], h[3]);
            *(float4*)&Ah[base + 4] = make_float4(h[4], h[5], h[6], h[7]);
            *(float4*)&Al[base]     = make_float4(l[0], l[1], l[2], l[3]);
            *(float4*)&Al[base + 4] = make_float4(l[4], l[5], l[6], l[7]);
        }
        #pragma unroll
        for (int t = 0; t < 2; t++) {
            int kb = (bkg + 2 * t) * 4;
            float h[4], l[4];
            #pragma unroll
            for (int kk = 0; kk < 4; kk++) {
                h[kk] = tf32r(bv[t][kk]);
                l[kk] = tf32r(bv[t][kk] - h[kk]);
            }
            int base = bn * PAD + kb;
            *(float4*)&Bh[base] = make_float4(h[0], h[1], h[2], h[3]);
            *(float4*)&Bl[base] = make_float4(l[0], l[1], l[2], l[3]);
        }
        __syncthreads();

        if (kc + 1 < nchunks) {
            int ko = (kc + 1) * 16;
            av0 = *(const float4*)(Ap + ko);
            av1 = *(const float4*)(Ap + ko + 4);
            #pragma unroll
            for (int t = 0; t < 2; t++) {
                int kb = ko + (bkg + 2 * t) * 4;
                #pragma unroll
                for (int kk = 0; kk < 4; kk++)
                    bv[t][kk] = Bp[(size_t)(kb + kk) * N];
            }
        }

        #pragma unroll
        for (int ks = 0; ks < 2; ks++) {
            unsigned int ah[2][4], al[2][4];
            #pragma unroll
            for (int mt = 0; mt < 2; mt++) {
                int r = warp_m * 32 + mt * 16 + g;
                int i0 = r * PAD + ks * 8 + q;
                ah[mt][0] = Ah32[i0];
                ah[mt][1] = Ah32[i0 + 8 * PAD];
                ah[mt][2] = Ah32[i0 + 4];
                ah[mt][3] = Ah32[i0 + 8 * PAD + 4];
                al[mt][0] = Al32[i0];
                al[mt][1] = Al32[i0 + 8 * PAD];
                al[mt][2] = Al32[i0 + 4];
                al[mt][3] = Al32[i0 + 8 * PAD + 4];
            }
            #pragma unroll
            for (int nt = 0; nt < 8; nt++) {
                int rc = warp_n * 64 + nt * 8 + g;
                int bi = rc * PAD + ks * 8 + q;
                unsigned int bh0 = Bh32[bi], bh1 = Bh32[bi + 4];
                unsigned int bl0 = Bl32[bi], bl1 = Bl32[bi + 4];
                #pragma unroll
                for (int mt = 0; mt < 2; mt++) {
                    mma_tf32(acc[mt][nt], ah[mt], bh0, bh1);
                    mma_tf32(acc[mt][nt], ah[mt], bl0, bl1);
                    mma_tf32(acc[mt][nt], al[mt], bh0, bh1);
                }
            }
        }
        __syncthreads();
    }

    #pragma unroll
    for (int mt = 0; mt < 2; mt++) {
        int row = bm0 + warp_m * 32 + mt * 16 + g;
        #pragma unroll
        for (int nt = 0; nt < 8; nt++) {
            int col = bn0 + warp_n * 64 + nt * 8 + 2 * q;
            float2 bb = *(const float2*)&bias[col];
            float2 c0 = make_float2(acc[mt][nt][0] + bb.x, acc[mt][nt][1] + bb.y);
            float2 c1 = make_float2(acc[mt][nt][2] + bb.x, acc[mt][nt][3] + bb.y);
            *(float2*)&C[(size_t)row * N + col]       = c0;
            *(float2*)&C[(size_t)(row + 8) * N + col] = c1;
        }
    }
}

// ---------------- row L2 norm for tokens: g_Pin -> g_A (fp32) + g_Abf (bf16) ----------------
__global__ void k_rownorm() {
    int rw = blockIdx.x, t = threadIdx.x;
    float4 v = ((const float4*)(g_Pin + (size_t)rw * LDIM))[t];
    float s = blockSum(v.x*v.x + v.y*v.y + v.z*v.z + v.w*v.w, 128);
    float r = rsqrtf(s + 1e-12f);
    float4 o = make_float4(v.x*r, v.y*r, v.z*r, v.w*r);
    ((float4*)(g_A + (size_t)rw * LDIM))[t] = o;
    __nv_bfloat162* ob = (__nv_bfloat162*)(g_Abf + (size_t)rw * LDIM);
    ob[t * 2 + 0] = __floats2bfloat162_rn(o.x, o.y);
    ob[t * 2 + 1] = __floats2bfloat162_rn(o.z, o.w);
}

// codes: double normalization (matches reference), exact ||b||^2, fp32 + bf16 copies
__global__ void k_codenorm() {
    int rw = blockIdx.x, t = threadIdx.x;
    float4 v = ((const float4*)(g_Pcode + (size_t)rw * LDIM))[t];
    float s1 = blockSum(v.x*v.x + v.y*v.y + v.z*v.z + v.w*v.w, 128);
    float r1 = rsqrtf(s1 + 1e-12f);
    v = make_float4(v.x*r1, v.y*r1, v.z*r1, v.w*r1);
    float s2 = blockSum(v.x*v.x + v.y*v.y + v.z*v.z + v.w*v.w, 128);
    float r2 = rsqrtf(s2 + 1e-12f);
    v = make_float4(v.x*r2, v.y*r2, v.z*r2, v.w*r2);
    float s3 = blockSum(v.x*v.x + v.y*v.y + v.z*v.z + v.w*v.w, 128);
    ((float4*)(g_C + (size_t)rw * LDIM))[t] = v;
    __nv_bfloat162* ob = (__nv_bfloat162*)(g_Cbf + (size_t)rw * LDIM);
    ob[t * 2 + 0] = __floats2bfloat162_rn(v.x, v.y);
    ob[t * 2 + 1] = __floats2bfloat162_rn(v.z, v.w);
    if (t == 0) g_b2[rw] = s3;
}

// ---------------- bf16 tensor-core scorer, cp.async depth-2 pipeline ----------------
// Also records per (token-row, code-tile) min into g_tmin for k_select's
// tile-skip filter (the value is already produced by the epilogue reduction).
__global__ __launch_bounds__(256) void k_score() {
    extern __shared__ __align__(16) char dsm[];
    __shared__ unsigned long long red[128 * 2];

    const int tid = threadIdx.x;
    const int wid = tid >> 5, lane = tid & 31;
    const int warp_m = wid >> 1, warp_n = wid & 1;
    const int g = lane >> 2, q = lane & 3;
    const int bm0 = blockIdx.y * 128;   // token tile
    const int bv0 = blockIdx.x * 128;   // code tile

    float acc[2][8][4];
    #pragma unroll
    for (int mt = 0; mt < 2; mt++)
        #pragma unroll
        for (int nt = 0; nt < 8; nt++)
            #pragma unroll
            for (int i = 0; i < 4; i++) acc[mt][nt][i] = 0.f;

    const uint4* Ag = (const uint4*)(g_Abf + (size_t)bm0 * LDIM);
    const uint4* Cg = (const uint4*)(g_Cbf + (size_t)bv0 * LDIM);
    const unsigned int sbase = (unsigned int)__cvta_generic_to_shared(dsm);

    int lrow[4], lwq[4];
    unsigned int ldst[4];
    #pragma unroll
    for (int i = 0; i < 4; i++) {
        int idx = tid + i * 256;
        lrow[i] = idx >> 3;
        lwq[i]  = idx & 7;
        ldst[i] = (unsigned int)((lrow[i] * 8 + (lwq[i] ^ (lrow[i] & 7))) * 16);
    }

    auto issue = [&](int kc) {
        unsigned int ab = sbase + (kc & 1) * SC_STAGE_BYTES;
        unsigned int cb2 = ab + 16384;
        #pragma unroll
        for (int i = 0; i < 4; i++) {
            const uint4* sa = Ag + (size_t)lrow[i] * 64 + kc * 8 + lwq[i];
            const uint4* sc = Cg + (size_t)lrow[i] * 64 + kc * 8 + lwq[i];
            cp16(ab  + ldst[i], sa);
            cp16(cb2 + ldst[i], sc);
        }
        CP_COMMIT();
    };

    issue(0);
    #pragma unroll
    for (int kc = 0; kc < 8; kc++) {
        if (kc + 1 < 8) { issue(kc + 1); CP_WAIT(1); }
        else            { CP_WAIT(0); }
        __syncthreads();

        const char* st = dsm + (kc & 1) * SC_STAGE_BYTES;
        const unsigned int* As32 = (const unsigned int*)st;
        const unsigned int* Cs32 = (const unsigned int*)(st + 16384);

        #pragma unroll
        for (int ks = 0; ks < 4; ks++) {
            unsigned int af[2][4];
            #pragma unroll
            for (int mt = 0; mt < 2; mt++) {
                int r0 = warp_m * 32 + mt * 16 + g;
                int r1 = r0 + 8;
                af[mt][0] = As32[r0*32 + (((ks*2 + 0) ^ (r0 & 7)) << 2) + q];
                af[mt][1] = As32[r1*32 + (((ks*2 + 0) ^ (r1 & 7)) << 2) + q];
                af[mt][2] = As32[r0*32 + (((ks*2 + 1) ^ (r0 & 7)) << 2) + q];
                af[mt][3] = As32[r1*32 + (((ks*2 + 1) ^ (r1 & 7)) << 2) + q];
            }
            #pragma unroll
            for (int nt = 0; nt < 8; nt++) {
                int rc = warp_n * 64 + nt * 8 + g;
                unsigned int b0 = Cs32[rc*32 + (((ks*2 + 0) ^ (rc & 7)) << 2) + q];
                unsigned int b1 = Cs32[rc*32 + (((ks*2 + 1) ^ (rc & 7)) << 2) + q];
                mma16816(acc[0][nt], af[0], b0, b1);
                mma16816(acc[1][nt], af[1], b0, b1);
            }
        }
        __syncthreads();
    }

    // epilogue: scores, fp16 store, per-row approx min (+ tile-min record)
    unsigned long long km[2][2];
    km[0][0] = km[0][1] = km[1][0] = km[1][1] = 0xFFFFFFFFFFFFFFFFull;

    #pragma unroll
    for (int nt = 0; nt < 8; nt++) {
        int colG = bv0 + warp_n * 64 + nt * 8 + q * 2;
        float2 bb = *(const float2*)&g_b2[colG];
        #pragma unroll
        for (int mt = 0; mt < 2; mt++) {
            float s0 = bb.x - 2.f * acc[mt][nt][0];
            float s1 = bb.y - 2.f * acc[mt][nt][1];
            float s2 = bb.x - 2.f * acc[mt][nt][2];
            float s3 = bb.y - 2.f * acc[mt][nt][3];
            int r0 = bm0 + warp_m * 32 + mt * 16 + g;
            *(__half2*)&g_S[(size_t)r0 * VSZ + colG]       = __floats2half2_rn(s0, s1);
            *(__half2*)&g_S[(size_t)(r0 + 8) * VSZ + colG] = __floats2half2_rn(s2, s3);
            unsigned long long p0 =
                ((unsigned long long)fkey(s0) << 32) | (unsigned int)colG;
            unsigned long long p1 =
                ((unsigned long long)fkey(s1) << 32) | (unsigned int)(colG + 1);
            if (p1 < p0) p0 = p1;
            if (p0 < km[mt][0]) km[mt][0] = p0;
            unsigned long long p2 =
                ((unsigned long long)fkey(s2) << 32) | (unsigned int)colG;
            unsigned long long p3 =
                ((unsigned long long)fkey(s3) << 32) | (unsigned int)(colG + 1);
            if (p3 < p2) p2 = p3;
            if (p2 < km[mt][1]) km[mt][1] = p2;
        }
    }
    #pragma unroll
    for (int mt = 0; mt < 2; mt++)
        #pragma unroll
        for (int h = 0; h < 2; h++) {
            unsigned long long v = km[mt][h];
            #pragma unroll
            for (int off = 1; off < 4; off <<= 1) {
                unsigned long long o = __shfl_xor_sync(0xffffffffu, v, off);
                if (o < v) v = o;
            }
            km[mt][h] = v;
        }
    if (q == 0) {
        #pragma unroll
        for (int mt = 0; mt < 2; mt++)
            #pragma unroll
            for (int h = 0; h < 2; h++) {
                int r = warp_m * 32 + mt * 16 + h * 8 + g;
                red[r * 2 + warp_n] = km[mt][h];
            }
    }
    __syncthreads();
    if (tid < 128) {
        unsigned long long m = red[tid * 2];
        if (red[tid * 2 + 1] < m) m = red[tid * 2 + 1];
        atomicMin(&g_best[bm0 + tid], m);
        // record this tile's min score for the select-phase tile filter
        g_tmin[(size_t)(bm0 + tid) * NTILE + blockIdx.x] =
            keyfloat((unsigned int)(m >> 32));
    }
}

// ---------------- candidate filter + exact fp32 rescore (one block per token) ----------------
// Tile-skip: only scan 128-score segments whose recorded tile-min <= thr.
// Identical candidate set (skipped tiles contain no score <= thr).
__global__ __launch_bounds__(256) void k_select() {
    const int n = blockIdx.x, tid = threadIdx.x;
    __shared__ int cnt;
    __shared__ int cand[256];
    __shared__ int qtile[NTILE];
    __shared__ int nqt;
    __shared__ unsigned long long bestSh;
    if (tid == 0) { cnt = 0; nqt = 0; bestSh = 0xFFFFFFFFFFFFFFFFull; }
    __syncthreads();

    const float thr = keyfloat((unsigned int)(g_best[n] >> 32)) + DELTA;

    // qualifying tiles (64 tile-mins = 256B read)
    if (tid < NTILE) {
        float tm = g_tmin[(size_t)n * NTILE + tid];
        if (tm <= thr) { int p = atomicAdd(&nqt, 1); qtile[p] = tid; }
    }
    __syncthreads();

    // scan only qualifying tiles' scores
    const __half* rowS = g_S + (size_t)n * VSZ;
    for (int ti = 0; ti < nqt; ti++) {
        int t0 = qtile[ti] * 128;
        if (tid < 128) {
            float f = __half2float(rowS[t0 + tid]);
            if (f <= thr) { int p = atomicAdd(&cnt, 1); if (p < 256) cand[p] = t0 + tid; }
        }
    }
    __syncthreads();
    int c = cnt;

    unsigned long long best = 0xFFFFFFFFFFFFFFFFull;
    if (c <= 256) {
        const float* ar = g_A + (size_t)n * LDIM;
        for (int i = 0; i < c; i++) {
            int v = cand[i];
            const float* cr = g_C + (size_t)v * LDIM;
            float part = ar[tid * 2] * cr[tid * 2] + ar[tid * 2 + 1] * cr[tid * 2 + 1];
            float s = blockSum(part, 256);
            float score = g_b2[v] - 2.f * s;
            unsigned long long p =
                ((unsigned long long)fkey(score) << 32) | (unsigned int)v;
            if (p < best) best = p;
        }
    } else {
        // safety fallback (statistically never): full exact scan for this token
        const float* ar = g_A + (size_t)n * LDIM;
        unsigned long long loc = 0xFFFFFFFFFFFFFFFFull;
        for (int v = tid; v < VSZ; v += 256) {
            const float* cr = g_C + (size_t)v * LDIM;
            float s = 0.f;
            for (int d = 0; d < LDIM; d++) s += ar[d] * cr[d];
            float score = g_b2[v] - 2.f * s;
            unsigned long long p =
                ((unsigned long long)fkey(score) << 32) | (unsigned int)v;
            if (p < loc) loc = p;
        }
        atomicMin(&bestSh, loc);
        __syncthreads();
        best = bestSh;
    }

    if (tid == 0) {
        int id = (int)(best & 0xFFFFFFFFull);
        g_idx[n] = id;
        atomicAdd(&g_count[id], 1);
    }
}

// ---------------- quantized_st output + commit MSE ----------------
__global__ void k_quant(const float* __restrict__ x, const float* __restrict__ cb,
                        float* __restrict__ out)
{
    int n = blockIdx.x, t = threadIdx.x;
    int id = g_idx[n];
    float4 xv = ((const float4*)(x  + (size_t)n  * DDIM))[t];
    float4 qv = ((const float4*)(cb + (size_t)id * DDIM))[t];
    float4 d = make_float4(qv.x - xv.x, qv.y - xv.y, qv.z - xv.z, qv.w - xv.w);
    ((float4*)(out + (size_t)n * DDIM))[t] =
        make_float4(xv.x + d.x, xv.y + d.y, xv.z + d.z, xv.w + d.w);
    float loc = d.x*d.x + d.y*d.y + d.z*d.z + d.w*d.w;
    float s = blockSum(loc, 256);
    if (t == 0) atomicAdd(&g_sum1, (double)s);
}

// ---------------- latent-space MSE ----------------
__global__ void k_l2loss() {
    int n = blockIdx.x, t = threadIdx.x;
    int id = g_idx[n];
    float4 a = ((const float4*)(g_Pin   + (size_t)n  * LDIM))[t];
    float4 b = ((const float4*)(g_Pcode + (size_t)id * LDIM))[t];
    float4 d = make_float4(b.x - a.x, b.y - a.y, b.z - a.z, b.w - a.w);
    float loc = d.x*d.x + d.y*d.y + d.z*d.z + d.w*d.w;
    float s = blockSum(loc, 128);
    if (t == 0) atomicAdd(&g_sum2, (double)s);
}

// ---------------- final scalars: loss, perplexity, usage ----------------
__global__ void k_final(float* __restrict__ outScal) {
    __shared__ double shd[256];
    __shared__ int    shi[256];
    int t = threadIdx.x;
    double lp = 0.0;
    int used = 0;
    for (int v = t; v < VSZ; v += 256) {
        int c = g_count[v];
        if (c > 0) used++;
        float p = (float)c * (1.0f / 8192.0f);
        lp += (double)(-(p * logf(p + 1e-10f)));
    }
    shd[t] = lp; shi[t] = used;
    __syncthreads();
    for (int o = 128; o; o >>= 1) {
        if (t < o) { shd[t] += shd[t + o]; shi[t] += shi[t + o]; }
        __syncthreads();
    }
    if (t == 0) {
        float lpf = (float)shd[0];
        float m1 = (float)(g_sum1 / (double)((size_t)NTOK * DDIM));
        float m2 = (float)(g_sum2 / (double)((size_t)NTOK * LDIM));
        float loss = (0.25f * m1 + m1) + (0.25f * m2 + m2) + 0.1f * lpf;
        outScal[0] = loss;
        outScal[1] = expf(lpf);
        outScal[2] = (float)shi[0] / (float)VSZ;
    }
}

// ---------------- launch ----------------
extern "C" void kernel_launch(void* const* d_in, const int* in_sizes, int n_in,
                              void* d_out, int out_size)
{
    (void)in_sizes; (void)n_in;
    const float* x      = (const float*)d_in[0];
    const float* cb     = (const float*)d_in[1];
    const float* W_in   = (const float*)d_in[2];
    const float* b_in   = (const float*)d_in[3];
    const float* W_code = (const float*)d_in[4];
    const float* b_code = (const float*)d_in[5];
    float* out = (float*)d_out;

    void *pPin, *pPcode;
    cudaGetSymbolAddress(&pPin,   g_Pin);
    cudaGetSymbolAddress(&pPcode, g_Pcode);

    // opt-in to 64KB dynamic smem for k_score (host attr — deterministic, no alloc)
    cudaFuncSetAttribute(k_score, cudaFuncAttributeMaxDynamicSharedMemorySize,
                         SC_SMEM_BYTES);

    k_init<<<(VSZ + 255) / 256, 256>>>();

    // latent_input = l2norm(x @ W_in + b_in); fp32-faithful tf32 3-pass GEMM
    k_gemm_tf32<<<dim3(LDIM / 128, NTOK / 128), 256>>>(
        x, W_in, b_in, (float*)pPin, NTOK, LDIM, DDIM);
    k_rownorm<<<NTOK, 128>>>();

    // latent_code (double-normalized) + exact ||b||^2
    k_gemm_tf32<<<dim3(LDIM / 128, VSZ / 128), 256>>>(
        cb, W_code, b_code, (float*)pPcode, VSZ, LDIM, DDIM);
    k_codenorm<<<VSZ, 128>>>();

    // bf16 tensor-core scoring (cp.async pipelined): fp16 scores + tile mins + approx min
    k_score<<<dim3(VSZ / 128, NTOK / 128), 256, SC_SMEM_BYTES>>>();

    // tile-filtered epsilon-select + exact fp32 rescore -> indices + histogram
    k_select<<<NTOK, 256>>>();

    k_quant<<<NTOK, 256>>>(x, cb, out);
    k_l2loss<<<NTOK, 128>>>();
    k_final<<<1, 256>>>(out + (out_size - 3));
}

// round 17
// speedup vs baseline: 1.2975x; 1.0213x over previous
#include <cuda_runtime.h>
#include <cuda_bf16.h>
#include <cuda_fp16.h>
#include <math.h>

// Problem constants
#define NTOK 8192   // B*T
#define DDIM 1024   // D
#define LDIM 512    // L
#define VSZ  8192   // V
#define NTILE (VSZ / 128)   // 64 code tiles per token row

// Filter margin for the bf16 scorer (see R7 analysis)
#define DELTA 0.02f

// smem row pad (floats) for the tf32 GEMM: bank = (4*row + q) % 32 -> conflict-free
#define PAD 20

// k_score double-buffer geometry: stage = As(16KB) + Cs(16KB)
#define SC_STAGE_BYTES 32768
#define SC_SMEM_BYTES  (2 * SC_STAGE_BYTES)   // 65536 dynamic

// ---------------- scratch (static __device__ — no runtime allocation) ----------------
__device__ float g_Pin  [NTOK * LDIM];   // x@W_in + b_in (pre-norm)
__device__ float g_A    [NTOK * LDIM];   // l2norm(P_in)          (fp32, exact rescore)
__device__ float g_Pcode[VSZ  * LDIM];   // codebook@W_code + b_code (pre-norm)
__device__ float g_C    [VSZ  * LDIM];   // l2norm(l2norm(P_code)) (fp32, exact rescore)
__device__ __nv_bfloat16 g_Abf[NTOK * LDIM];  // bf16 copy for MMA scorer
__device__ __nv_bfloat16 g_Cbf[VSZ  * LDIM];  // bf16 copy for MMA scorer
__device__ __half g_S[(size_t)NTOK * VSZ];    // approx scores (fp16), 134MB
__device__ float g_tmin[NTOK * NTILE];   // per (token, code-tile) approx min (2MB)
__device__ float g_b2   [VSZ];           // sum(C*C) per code row (exact)
__device__ unsigned long long g_best[NTOK];   // packed approx min (key<<32 | idx)
__device__ int    g_idx  [NTOK];
__device__ int    g_count[VSZ];
__device__ double g_sum1;                // sum (q - x)^2 over N*D
__device__ double g_sum2;                // sum (Pcode[idx] - Pin)^2 over N*L

// ---------------- helpers ----------------
__device__ __forceinline__ unsigned int fkey(float f) {
    unsigned int u = __float_as_uint(f);
    return (u & 0x80000000u) ? ~u : (u | 0x80000000u);   // order-preserving map
}
__device__ __forceinline__ float keyfloat(unsigned int k) {
    unsigned int u = (k & 0x80000000u) ? (k & 0x7FFFFFFFu) : ~k;
    return __uint_as_float(u);
}

// block sum; all threads receive the result
__device__ __forceinline__ float blockSum(float v, int nthreads) {
    __shared__ float sh[8];
    int lane = threadIdx.x & 31, w = threadIdx.x >> 5, nw = nthreads >> 5;
    #pragma unroll
    for (int o = 16; o; o >>= 1) v += __shfl_down_sync(0xffffffffu, v, o);
    if (lane == 0) sh[w] = v;
    __syncthreads();
    float r = 0.f;
    if (threadIdx.x == 0) {
        for (int i = 0; i < nw; i++) r += sh[i];
        sh[0] = r;
    }
    __syncthreads();
    r = sh[0];
    __syncthreads();
    return r;
}

__device__ __forceinline__ void mma16816(float* c, const unsigned int* a,
                                         unsigned int b0, unsigned int b1) {
    asm volatile(
        "mma.sync.aligned.m16n8k16.row.col.f32.bf16.bf16.f32 "
        "{%0,%1,%2,%3},{%4,%5,%6,%7},{%8,%9},{%0,%1,%2,%3};"
        : "+f"(c[0]), "+f"(c[1]), "+f"(c[2]), "+f"(c[3])
        : "r"(a[0]), "r"(a[1]), "r"(a[2]), "r"(a[3]), "r"(b0), "r"(b1));
}

__device__ __forceinline__ void mma_tf32(float* c, const unsigned int* a,
                                         unsigned int b0, unsigned int b1) {
    asm volatile(
        "mma.sync.aligned.m16n8k8.row.col.f32.tf32.tf32.f32 "
        "{%0,%1,%2,%3},{%4,%5,%6,%7},{%8,%9},{%0,%1,%2,%3};"
        : "+f"(c[0]), "+f"(c[1]), "+f"(c[2]), "+f"(c[3])
        : "r"(a[0]), "r"(a[1]), "r"(a[2]), "r"(a[3]), "r"(b0), "r"(b1));
}

__device__ __forceinline__ float tf32r(float x) {
    float r; asm("cvt.rna.tf32.f32 %0, %1;" : "=f"(r) : "f"(x)); return r;
}

__device__ __forceinline__ void cp16(unsigned int dst_smem, const void* src) {
    asm volatile("cp.async.cg.shared.global [%0], [%1], 16;\n"
                 :: "r"(dst_smem), "l"(src));
}
#define CP_COMMIT() asm volatile("cp.async.commit_group;\n" ::)
#define CP_WAIT(N)  asm volatile("cp.async.wait_group %0;\n" :: "n"(N))

// ldmatrix: 4x 8x8 b16 matrices, per-lane row addresses (lanes 0-7 -> m0, ...)
__device__ __forceinline__ void ldsm_x4(unsigned int addr, unsigned int* r) {
    asm volatile("ldmatrix.sync.aligned.m8n8.x4.shared.b16 {%0,%1,%2,%3}, [%4];"
        : "=r"(r[0]), "=r"(r[1]), "=r"(r[2]), "=r"(r[3]) : "r"(addr));
}

// ---------------- init ----------------
__global__ void k_init() {
    int i = blockIdx.x * blockDim.x + threadIdx.x;
    if (i < VSZ)  g_count[i] = 0;
    if (i < NTOK) g_best[i] = 0xFFFFFFFFFFFFFFFFull;
    if (i == 0) { g_sum1 = 0.0; g_sum2 = 0.0; }
}

// ---------------- tf32 3-pass GEMM (R14 version, unchanged) ----------------
__global__ __launch_bounds__(256, 2) void k_gemm_tf32(
    const float* __restrict__ A, const float* __restrict__ B,
    const float* __restrict__ bias, float* __restrict__ C,
    int M, int N, int K)
{
    __shared__ __align__(16) float Ah[128 * PAD], Al[128 * PAD];
    __shared__ __align__(16) float Bh[128 * PAD], Bl[128 * PAD];

    const int tid = threadIdx.x;
    const int lane = tid & 31;
    const int wid = tid >> 5;
    const int warp_m = wid >> 1, warp_n = wid & 1;
    const int g = lane >> 2, q = lane & 3;
    const int bm0 = blockIdx.y * 128, bn0 = blockIdx.x * 128;

    float acc[2][8][4];
    #pragma unroll
    for (int mt = 0; mt < 2; mt++)
        #pragma unroll
        for (int nt = 0; nt < 8; nt++)
            #pragma unroll
            for (int i = 0; i < 4; i++) acc[mt][nt][i] = 0.f;

    const int arow = tid >> 1, ahalf = (tid & 1) * 8;
    const float* Ap = A + (size_t)(bm0 + arow) * K + ahalf;
    const int bn = tid & 127, bkg = tid >> 7;
    const float* Bp = B + bn0 + bn;

    float4 av0 = *(const float4*)(Ap);
    float4 av1 = *(const float4*)(Ap + 4);
    float bv[2][4];
    #pragma unroll
    for (int t = 0; t < 2; t++) {
        int kb = (bkg + 2 * t) * 4;
        #pragma unroll
        for (int kk = 0; kk < 4; kk++)
            bv[t][kk] = Bp[(size_t)(kb + kk) * N];
    }

    const unsigned int* Ah32 = (const unsigned int*)Ah;
    const unsigned int* Al32 = (const unsigned int*)Al;
    const unsigned int* Bh32 = (const unsigned int*)Bh;
    const unsigned int* Bl32 = (const unsigned int*)Bl;

    const int nchunks = K / 16;
    for (int kc = 0; kc < nchunks; kc++) {
        {
            float va[8] = {av0.x, av0.y, av0.z, av0.w, av1.x, av1.y, av1.z, av1.w};
            float h[8], l[8];
            #pragma unroll
            for (int i = 0; i < 8; i++) {
                h[i] = tf32r(va[i]);
                l[i] = tf32r(va[i] - h[i]);
            }
            int base = arow * PAD + ahalf;
            *(float4*)&Ah[base]     = make_float4(h[0], h[1], h[2], h[3]);
            *(float4*)&Ah[base + 4] = make_float4(h[4], h[5], h[6], h[7]);
            *(float4*)&Al[base]     = make_float4(l[0], l[1], l[2], l[3]);
            *(float4*)&Al[base + 4] = make_float4(l[4], l[5], l[6], l[7]);
        }
        #pragma unroll
        for (int t = 0; t < 2; t++) {
            int kb = (bkg + 2 * t) * 4;
            float h[4], l[4];
            #pragma unroll
            for (int kk = 0; kk < 4; kk++) {
                h[kk] = tf32r(bv[t][kk]);
                l[kk] = tf32r(bv[t][kk] - h[kk]);
            }
            int base = bn * PAD + kb;
            *(float4*)&Bh[base] = make_float4(h[0], h[1], h[2], h[3]);
            *(float4*)&Bl[base] = make_float4(l[0], l[1], l[2], l[3]);
        }
        __syncthreads();

        if (kc + 1 < nchunks) {
            int ko = (kc + 1) * 16;
            av0 = *(const float4*)(Ap + ko);
            av1 = *(const float4*)(Ap + ko + 4);
            #pragma unroll
            for (int t = 0; t < 2; t++) {
                int kb = ko + (bkg + 2 * t) * 4;
                #pragma unroll
                for (int kk = 0; kk < 4; kk++)
                    bv[t][kk] = Bp[(size_t)(kb + kk) * N];
            }
        }

        #pragma unroll
        for (int ks = 0; ks < 2; ks++) {
            unsigned int ah[2][4], al[2][4];
            #pragma unroll
            for (int mt = 0; mt < 2; mt++) {
                int r = warp_m * 32 + mt * 16 + g;
                int i0 = r * PAD + ks * 8 + q;
                ah[mt][0] = Ah32[i0];
                ah[mt][1] = Ah32[i0 + 8 * PAD];
                ah[mt][2] = Ah32[i0 + 4];
                ah[mt][3] = Ah32[i0 + 8 * PAD + 4];
                al[mt][0] = Al32[i0];
                al[mt][1] = Al32[i0 + 8 * PAD];
                al[mt][2] = Al32[i0 + 4];
                al[mt][3] = Al32[i0 + 8 * PAD + 4];
            }
            #pragma unroll
            for (int nt = 0; nt < 8; nt++) {
                int rc = warp_n * 64 + nt * 8 + g;
                int bi = rc * PAD + ks * 8 + q;
                unsigned int bh0 = Bh32[bi], bh1 = Bh32[bi + 4];
                unsigned int bl0 = Bl32[bi], bl1 = Bl32[bi + 4];
                #pragma unroll
                for (int mt = 0; mt < 2; mt++) {
                    mma_tf32(acc[mt][nt], ah[mt], bh0, bh1);
                    mma_tf32(acc[mt][nt], ah[mt], bl0, bl1);
                    mma_tf32(acc[mt][nt], al[mt], bh0, bh1);
                }
            }
        }
        __syncthreads();
    }

    #pragma unroll
    for (int mt = 0; mt < 2; mt++) {
        int row = bm0 + warp_m * 32 + mt * 16 + g;
        #pragma unroll
        for (int nt = 0; nt < 8; nt++) {
            int col = bn0 + warp_n * 64 + nt * 8 + 2 * q;
            float2 bb = *(const float2*)&bias[col];
            float2 c0 = make_float2(acc[mt][nt][0] + bb.x, acc[mt][nt][1] + bb.y);
            float2 c1 = make_float2(acc[mt][nt][2] + bb.x, acc[mt][nt][3] + bb.y);
            *(float2*)&C[(size_t)row * N + col]       = c0;
            *(float2*)&C[(size_t)(row + 8) * N + col] = c1;
        }
    }
}

// ---------------- row L2 norm for tokens ----------------
__global__ void k_rownorm() {
    int rw = blockIdx.x, t = threadIdx.x;
    float4 v = ((const float4*)(g_Pin + (size_t)rw * LDIM))[t];
    float s = blockSum(v.x*v.x + v.y*v.y + v.z*v.z + v.w*v.w, 128);
    float r = rsqrtf(s + 1e-12f);
    float4 o = make_float4(v.x*r, v.y*r, v.z*r, v.w*r);
    ((float4*)(g_A + (size_t)rw * LDIM))[t] = o;
    __nv_bfloat162* ob = (__nv_bfloat162*)(g_Abf + (size_t)rw * LDIM);
    ob[t * 2 + 0] = __floats2bfloat162_rn(o.x, o.y);
    ob[t * 2 + 1] = __floats2bfloat162_rn(o.z, o.w);
}

// codes: double normalization (matches reference), exact ||b||^2
__global__ void k_codenorm() {
    int rw = blockIdx.x, t = threadIdx.x;
    float4 v = ((const float4*)(g_Pcode + (size_t)rw * LDIM))[t];
    float s1 = blockSum(v.x*v.x + v.y*v.y + v.z*v.z + v.w*v.w, 128);
    float r1 = rsqrtf(s1 + 1e-12f);
    v = make_float4(v.x*r1, v.y*r1, v.z*r1, v.w*r1);
    float s2 = blockSum(v.x*v.x + v.y*v.y + v.z*v.z + v.w*v.w, 128);
    float r2 = rsqrtf(s2 + 1e-12f);
    v = make_float4(v.x*r2, v.y*r2, v.z*r2, v.w*r2);
    float s3 = blockSum(v.x*v.x + v.y*v.y + v.z*v.z + v.w*v.w, 128);
    ((float4*)(g_C + (size_t)rw * LDIM))[t] = v;
    __nv_bfloat162* ob = (__nv_bfloat162*)(g_Cbf + (size_t)rw * LDIM);
    ob[t * 2 + 0] = __floats2bfloat162_rn(v.x, v.y);
    ob[t * 2 + 1] = __floats2bfloat162_rn(v.z, v.w);
    if (t == 0) g_b2[rw] = s3;
}

// ---------------- bf16 scorer: cp.async pipeline + ldmatrix fragments ----------------
// Tile 128 tokens x 128 codes, K=512 in 8 chunks of 64. 8 warps: 4(m) x 2(n).
// cp.async double-buffered stages (XOR-swizzled = conflict-free); fragment loads
// via ldmatrix.x4 (24 LDSM/chunk/warp replacing 96 LDS.32 — shared-pipe cut).
__global__ __launch_bounds__(256) void k_score() {
    extern __shared__ __align__(16) char dsm[];
    __shared__ unsigned long long red[128 * 2];

    const int tid = threadIdx.x;
    const int wid = tid >> 5, lane = tid & 31;
    const int warp_m = wid >> 1, warp_n = wid & 1;
    const int g = lane >> 2, q = lane & 3;
    const int bm0 = blockIdx.y * 128;   // token tile
    const int bv0 = blockIdx.x * 128;   // code tile

    float acc[2][8][4];
    #pragma unroll
    for (int mt = 0; mt < 2; mt++)
        #pragma unroll
        for (int nt = 0; nt < 8; nt++)
            #pragma unroll
            for (int i = 0; i < 4; i++) acc[mt][nt][i] = 0.f;

    const uint4* Ag = (const uint4*)(g_Abf + (size_t)bm0 * LDIM);
    const uint4* Cg = (const uint4*)(g_Cbf + (size_t)bv0 * LDIM);
    const unsigned int sbase = (unsigned int)__cvta_generic_to_shared(dsm);

    // loader mapping (4 x 16B per array per chunk per thread)
    int lrow[4], lwq[4];
    unsigned int ldst[4];
    #pragma unroll
    for (int i = 0; i < 4; i++) {
        int idx = tid + i * 256;
        lrow[i] = idx >> 3;
        lwq[i]  = idx & 7;
        ldst[i] = (unsigned int)((lrow[i] * 8 + (lwq[i] ^ (lrow[i] & 7))) * 16);
    }

    auto issue = [&](int kc) {
        unsigned int ab = sbase + (kc & 1) * SC_STAGE_BYTES;
        unsigned int cb2 = ab + 16384;
        #pragma unroll
        for (int i = 0; i < 4; i++) {
            const uint4* sa = Ag + (size_t)lrow[i] * 64 + kc * 8 + lwq[i];
            const uint4* sc = Cg + (size_t)lrow[i] * 64 + kc * 8 + lwq[i];
            cp16(ab  + ldst[i], sa);
            cp16(cb2 + ldst[i], sc);
        }
        CP_COMMIT();
    };

    // ldmatrix per-lane address precompute.
    // A x4: m0 rows+0 k0 / m1 rows+8 k0 / m2 rows+0 k1 / m3 rows+8 k1
    const int lmat = lane >> 3, lr = lane & 7;
    const int rA = warp_m * 32 + (lmat & 1) * 8 + lr;   // mt=0 rows; mt=1 = +16
    const int kaddA = lmat >> 1;                        // k-half of the 16-k step
    // B x4: m0 (nt,k0) / m1 (nt,k1) / m2 (nt+1,k0) / m3 (nt+1,k1)
    const int rB = warp_n * 64 + ((lane >> 4) & 1) * 8 + lr;  // nt pair base rows
    const int kaddB = (lane >> 3) & 1;

    issue(0);
    #pragma unroll
    for (int kc = 0; kc < 8; kc++) {
        if (kc + 1 < 8) { issue(kc + 1); CP_WAIT(1); }
        else            { CP_WAIT(0); }
        __syncthreads();

        const unsigned int stA = sbase + (kc & 1) * SC_STAGE_BYTES;
        const unsigned int stB = stA + 16384;

        #pragma unroll
        for (int ks = 0; ks < 4; ks++) {
            unsigned int af[2][4];
            unsigned int uA = (unsigned)(ks * 2 + kaddA);
            unsigned int aaddr = stA + rA * 128 + ((uA ^ (rA & 7)) << 4);
            ldsm_x4(aaddr, af[0]);
            ldsm_x4(aaddr + 2048, af[1]);      // +16 rows: row&7 preserved
            unsigned int uB = (unsigned)(ks * 2 + kaddB);
            unsigned int baddr = stB + rB * 128 + ((uB ^ (rB & 7)) << 4);
            #pragma unroll
            for (int np = 0; np < 4; np++) {   // nt pairs {0,1},{2,3},{4,5},{6,7}
                unsigned int bf[4];
                ldsm_x4(baddr + np * 2048, bf);
                mma16816(acc[0][np * 2],     af[0], bf[0], bf[1]);
                mma16816(acc[1][np * 2],     af[1], bf[0], bf[1]);
                mma16816(acc[0][np * 2 + 1], af[0], bf[2], bf[3]);
                mma16816(acc[1][np * 2 + 1], af[1], bf[2], bf[3]);
            }
        }
        __syncthreads();
    }

    // epilogue: scores, fp16 store, per-row approx min (+ tile-min record)
    unsigned long long km[2][2];
    km[0][0] = km[0][1] = km[1][0] = km[1][1] = 0xFFFFFFFFFFFFFFFFull;

    #pragma unroll
    for (int nt = 0; nt < 8; nt++) {
        int colG = bv0 + warp_n * 64 + nt * 8 + q * 2;
        float2 bb = *(const float2*)&g_b2[colG];
        #pragma unroll
        for (int mt = 0; mt < 2; mt++) {
            float s0 = bb.x - 2.f * acc[mt][nt][0];
            float s1 = bb.y - 2.f * acc[mt][nt][1];
            float s2 = bb.x - 2.f * acc[mt][nt][2];
            float s3 = bb.y - 2.f * acc[mt][nt][3];
            int r0 = bm0 + warp_m * 32 + mt * 16 + g;
            *(__half2*)&g_S[(size_t)r0 * VSZ + colG]       = __floats2half2_rn(s0, s1);
            *(__half2*)&g_S[(size_t)(r0 + 8) * VSZ + colG] = __floats2half2_rn(s2, s3);
            unsigned long long p0 =
                ((unsigned long long)fkey(s0) << 32) | (unsigned int)colG;
            unsigned long long p1 =
                ((unsigned long long)fkey(s1) << 32) | (unsigned int)(colG + 1);
            if (p1 < p0) p0 = p1;
            if (p0 < km[mt][0]) km[mt][0] = p0;
            unsigned long long p2 =
                ((unsigned long long)fkey(s2) << 32) | (unsigned int)colG;
            unsigned long long p3 =
                ((unsigned long long)fkey(s3) << 32) | (unsigned int)(colG + 1);
            if (p3 < p2) p2 = p3;
            if (p2 < km[mt][1]) km[mt][1] = p2;
        }
    }
    #pragma unroll
    for (int mt = 0; mt < 2; mt++)
        #pragma unroll
        for (int h = 0; h < 2; h++) {
            unsigned long long v = km[mt][h];
            #pragma unroll
            for (int off = 1; off < 4; off <<= 1) {
                unsigned long long o = __shfl_xor_sync(0xffffffffu, v, off);
                if (o < v) v = o;
            }
            km[mt][h] = v;
        }
    if (q == 0) {
        #pragma unroll
        for (int mt = 0; mt < 2; mt++)
            #pragma unroll
            for (int h = 0; h < 2; h++) {
                int r = warp_m * 32 + mt * 16 + h * 8 + g;
                red[r * 2 + warp_n] = km[mt][h];
            }
    }
    __syncthreads();
    if (tid < 128) {
        unsigned long long m = red[tid * 2];
        if (red[tid * 2 + 1] < m) m = red[tid * 2 + 1];
        atomicMin(&g_best[bm0 + tid], m);
        g_tmin[(size_t)(bm0 + tid) * NTILE + blockIdx.x] =
            keyfloat((unsigned int)(m >> 32));
    }
}

// ---------------- tile-filtered select + exact fp32 rescore (R14 version) ----------------
__global__ __launch_bounds__(256) void k_select() {
    const int n = blockIdx.x, tid = threadIdx.x;
    __shared__ int cnt;
    __shared__ int cand[256];
    __shared__ int qtile[NTILE];
    __shared__ int nqt;
    __shared__ unsigned long long bestSh;
    if (tid == 0) { cnt = 0; nqt = 0; bestSh = 0xFFFFFFFFFFFFFFFFull; }
    __syncthreads();

    const float thr = keyfloat((unsigned int)(g_best[n] >> 32)) + DELTA;

    if (tid < NTILE) {
        float tm = g_tmin[(size_t)n * NTILE + tid];
        if (tm <= thr) { int p = atomicAdd(&nqt, 1); qtile[p] = tid; }
    }
    __syncthreads();

    const __half* rowS = g_S + (size_t)n * VSZ;
    for (int ti = 0; ti < nqt; ti++) {
        int t0 = qtile[ti] * 128;
        if (tid < 128) {
            float f = __half2float(rowS[t0 + tid]);
            if (f <= thr) { int p = atomicAdd(&cnt, 1); if (p < 256) cand[p] = t0 + tid; }
        }
    }
    __syncthreads();
    int c = cnt;

    unsigned long long best = 0xFFFFFFFFFFFFFFFFull;
    if (c <= 256) {
        const float* ar = g_A + (size_t)n * LDIM;
        for (int i = 0; i < c; i++) {
            int v = cand[i];
            const float* cr = g_C + (size_t)v * LDIM;
            float part = ar[tid * 2] * cr[tid * 2] + ar[tid * 2 + 1] * cr[tid * 2 + 1];
            float s = blockSum(part, 256);
            float score = g_b2[v] - 2.f * s;
            unsigned long long p =
                ((unsigned long long)fkey(score) << 32) | (unsigned int)v;
            if (p < best) best = p;
        }
    } else {
        const float* ar = g_A + (size_t)n * LDIM;
        unsigned long long loc = 0xFFFFFFFFFFFFFFFFull;
        for (int v = tid; v < VSZ; v += 256) {
            const float* cr = g_C + (size_t)v * LDIM;
            float s = 0.f;
            for (int d = 0; d < LDIM; d++) s += ar[d] * cr[d];
            float score = g_b2[v] - 2.f * s;
            unsigned long long p =
                ((unsigned long long)fkey(score) << 32) | (unsigned int)v;
            if (p < loc) loc = p;
        }
        atomicMin(&bestSh, loc);
        __syncthreads();
        best = bestSh;
    }

    if (tid == 0) {
        int id = (int)(best & 0xFFFFFFFFull);
        g_idx[n] = id;
        atomicAdd(&g_count[id], 1);
    }
}

// ---------------- quantized_st output + commit MSE ----------------
__global__ void k_quant(const float* __restrict__ x, const float* __restrict__ cb,
                        float* __restrict__ out)
{
    int n = blockIdx.x, t = threadIdx.x;
    int id = g_idx[n];
    float4 xv = ((const float4*)(x  + (size_t)n  * DDIM))[t];
    float4 qv = ((const float4*)(cb + (size_t)id * DDIM))[t];
    float4 d = make_float4(qv.x - xv.x, qv.y - xv.y, qv.z - xv.z, qv.w - xv.w);
    ((float4*)(out + (size_t)n * DDIM))[t] =
        make_float4(xv.x + d.x, xv.y + d.y, xv.z + d.z, xv.w + d.w);
    float loc = d.x*d.x + d.y*d.y + d.z*d.z + d.w*d.w;
    float s = blockSum(loc, 256);
    if (t == 0) atomicAdd(&g_sum1, (double)s);
}

// ---------------- latent-space MSE ----------------
__global__ void k_l2loss() {
    int n = blockIdx.x, t = threadIdx.x;
    int id = g_idx[n];
    float4 a = ((const float4*)(g_Pin   + (size_t)n  * LDIM))[t];
    float4 b = ((const float4*)(g_Pcode + (size_t)id * LDIM))[t];
    float4 d = make_float4(b.x - a.x, b.y - a.y, b.z - a.z, b.w - a.w);
    float loc = d.x*d.x + d.y*d.y + d.z*d.z + d.w*d.w;
    float s = blockSum(loc, 128);
    if (t == 0) atomicAdd(&g_sum2, (double)s);
}

// ---------------- final scalars ----------------
__global__ void k_final(float* __restrict__ outScal) {
    __shared__ double shd[256];
    __shared__ int    shi[256];
    int t = threadIdx.x;
    double lp = 0.0;
    int used = 0;
    for (int v = t; v < VSZ; v += 256) {
        int c = g_count[v];
        if (c > 0) used++;
        float p = (float)c * (1.0f / 8192.0f);
        lp += (double)(-(p * logf(p + 1e-10f)));
    }
    shd[t] = lp; shi[t] = used;
    __syncthreads();
    for (int o = 128; o; o >>= 1) {
        if (t < o) { shd[t] += shd[t + o]; shi[t] += shi[t + o]; }
        __syncthreads();
    }
    if (t == 0) {
        float lpf = (float)shd[0];
        float m1 = (float)(g_sum1 / (double)((size_t)NTOK * DDIM));
        float m2 = (float)(g_sum2 / (double)((size_t)NTOK * LDIM));
        float loss = (0.25f * m1 + m1) + (0.25f * m2 + m2) + 0.1f * lpf;
        outScal[0] = loss;
        outScal[1] = expf(lpf);
        outScal[2] = (float)shi[0] / (float)VSZ;
    }
}

// ---------------- launch ----------------
extern "C" void kernel_launch(void* const* d_in, const int* in_sizes, int n_in,
                              void* d_out, int out_size)
{
    (void)in_sizes; (void)n_in;
    const float* x      = (const float*)d_in[0];
    const float* cb     = (const float*)d_in[1];
    const float* W_in   = (const float*)d_in[2];
    const float* b_in   = (const float*)d_in[3];
    const float* W_code = (const float*)d_in[4];
    const float* b_code = (const float*)d_in[5];
    float* out = (float*)d_out;

    void *pPin, *pPcode;
    cudaGetSymbolAddress(&pPin,   g_Pin);
    cudaGetSymbolAddress(&pPcode, g_Pcode);

    cudaFuncSetAttribute(k_score, cudaFuncAttributeMaxDynamicSharedMemorySize,
                         SC_SMEM_BYTES);

    k_init<<<(VSZ + 255) / 256, 256>>>();

    k_gemm_tf32<<<dim3(LDIM / 128, NTOK / 128), 256>>>(
        x, W_in, b_in, (float*)pPin, NTOK, LDIM, DDIM);
    k_rownorm<<<NTOK, 128>>>();

    k_gemm_tf32<<<dim3(LDIM / 128, VSZ / 128), 256>>>(
        cb, W_code, b_code, (float*)pPcode, VSZ, LDIM, DDIM);
    k_codenorm<<<VSZ, 128>>>();

    // bf16 scoring (cp.async + ldmatrix): fp16 scores + tile mins + approx min
    k_score<<<dim3(VSZ / 128, NTOK / 128), 256, SC_SMEM_BYTES>>>();

    k_select<<<NTOK, 256>>>();

    k_quant<<<NTOK, 256>>>(x, cb, out);
    k_l2loss<<<NTOK, 128>>>();
    k_final<<<1, 256>>>(out + (out_size - 3));
}